// round 5
// baseline (speedup 1.0000x reference)
#include <cuda_runtime.h>
#include <cuda_bf16.h>
#include <stdint.h>

#define BATCH 8
#define SEQ1  2048
#define SEQ2  2048
#define DIM   1024
#define MASK_FILL_V (-100.0f)

using bf16 = __nv_bfloat16;

// ---------------- scratch (static __device__, no allocation) ----------------
__device__ bf16  g_in1h[(size_t)BATCH*SEQ1*DIM];
__device__ bf16  g_in1l[(size_t)BATCH*SEQ1*DIM];
__device__ bf16  g_in2h[(size_t)BATCH*SEQ2*DIM];
__device__ bf16  g_in2l[(size_t)BATCH*SEQ2*DIM];
__device__ bf16  g_wh[(size_t)DIM*DIM];
__device__ bf16  g_wl[(size_t)DIM*DIM];
__device__ bf16  g_o1h[(size_t)BATCH*SEQ1*DIM];
__device__ bf16  g_o1l[(size_t)BATCH*SEQ1*DIM];
__device__ bf16  g_t1h[(size_t)BATCH*DIM*SEQ1];   // input1^T split [B,D,S1]
__device__ bf16  g_t1l[(size_t)BATCH*DIM*SEQ1];
__device__ float g_scores[(size_t)BATCH*SEQ2*SEQ1];
__device__ bf16  g_ph[(size_t)BATCH*SEQ2*SEQ1];
__device__ bf16  g_pl[(size_t)BATCH*SEQ2*SEQ1];

__device__ __forceinline__ void split2(float x, bf16 &h, bf16 &l) {
    h = __float2bfloat16(x);
    l = __float2bfloat16(x - __bfloat162float(h));
}

// ---------------- small helper kernels ----------------
__global__ __launch_bounds__(256) void split_kernel(const float* __restrict__ x,
                                                    bf16* __restrict__ h,
                                                    bf16* __restrict__ l) {
    size_t i = ((size_t)blockIdx.x * 256 + threadIdx.x) * 4;
    float4 v = *(const float4*)(x + i);
    bf16 h0,h1,h2,h3,l0,l1,l2,l3;
    split2(v.x,h0,l0); split2(v.y,h1,l1); split2(v.z,h2,l2); split2(v.w,h3,l3);
    __nv_bfloat162 a, b;
    a.x=h0; a.y=h1; b.x=h2; b.y=h3;
    ((__nv_bfloat162*)(h+i))[0] = a; ((__nv_bfloat162*)(h+i))[1] = b;
    a.x=l0; a.y=l1; b.x=l2; b.y=l3;
    ((__nv_bfloat162*)(l+i))[0] = a; ((__nv_bfloat162*)(l+i))[1] = b;
}

// input1 [B,S1,D] fp32 -> transposed split [B,D,S1] bf16 hi/lo
__global__ __launch_bounds__(256)
void transpose_split(const float* __restrict__ x, bf16* __restrict__ th,
                     bf16* __restrict__ tl) {
    __shared__ float t[32][33];
    const int b  = blockIdx.z;
    const int s0 = blockIdx.x * 32, d0 = blockIdx.y * 32;
    const int tx = threadIdx.x & 31, ty = threadIdx.x >> 5;   // 8 rows/pass
    const float* xp = x + ((size_t)b * SEQ1 + s0) * DIM + d0;
#pragma unroll
    for (int k = 0; k < 4; k++)
        t[ty + 8*k][tx] = xp[(size_t)(ty + 8*k) * DIM + tx];
    __syncthreads();
    const size_t ob = ((size_t)b * DIM + d0) * SEQ1 + s0;
#pragma unroll
    for (int k = 0; k < 4; k++) {
        bf16 h, l; split2(t[tx][ty + 8*k], h, l);
        th[ob + (size_t)(ty + 8*k) * SEQ1 + tx] = h;
        tl[ob + (size_t)(ty + 8*k) * SEQ1 + tx] = l;
    }
}

// ---------------- PTX helpers ----------------
#define CP16(dst, src) asm volatile("cp.async.cg.shared.global [%0], [%1], 16;\n" :: "r"(dst), "l"(src))
#define CP_COMMIT()    asm volatile("cp.async.commit_group;\n")
#define CP_WAIT1()     asm volatile("cp.async.wait_group 1;\n")
#define CP_WAIT0()     asm volatile("cp.async.wait_group 0;\n")

#define MMA_BF16(d, a, b) asm volatile( \
  "mma.sync.aligned.m16n8k16.row.col.f32.bf16.bf16.f32 " \
  "{%0,%1,%2,%3},{%4,%5,%6,%7},{%8,%9},{%0,%1,%2,%3};\n" \
  : "+f"(d[0]), "+f"(d[1]), "+f"(d[2]), "+f"(d[3]) \
  : "r"(a[0]), "r"(a[1]), "r"(a[2]), "r"(a[3]), "r"(b[0]), "r"(b[1]))

#define LDSM_X4(r0, r1, r2, r3, addr) asm volatile( \
  "ldmatrix.sync.aligned.m8n8.x4.shared.b16 {%0,%1,%2,%3}, [%4];\n" \
  : "=r"(r0), "=r"(r1), "=r"(r2), "=r"(r3) : "r"(addr))

// ---------------------------------------------------------------------------
// Split-bf16 HMMA NT GEMM: C[M,N] = A[M,K]*B[N,K]^T, 3-product split
// (C += Ah*Bh + Ah*Bl + Al*Bh). 128x128 tile, BK=32, 256 threads, 8 warps
// (warp tile 64x32), 2-stage cp.async pipeline, ldmatrix fragment loads.
// smem rows padded to 40 halves (80B) -> conflict-free ldmatrix.
//   EPI=0: fp32 out.  EPI=1: fp32 out + column(N) mask.  EPI=2: split bf16 out.
// ---------------------------------------------------------------------------
template<int EPI>
__global__ __launch_bounds__(256, 2)
void gemm_mma(const bf16* __restrict__ Ahg, const bf16* __restrict__ Alg,
              const bf16* __restrict__ Bhg, const bf16* __restrict__ Blg,
              float* __restrict__ Cfg, bf16* __restrict__ Chg, bf16* __restrict__ Clg,
              const unsigned int* __restrict__ maskg,
              int M, int N, int K,
              size_t sA, size_t sB, size_t sC, size_t sMask)
{
    extern __shared__ __align__(16) char dsm[];
    const uint32_t smem0 = (uint32_t)__cvta_generic_to_shared(dsm);
    // per stage: 4 arrays (Ah, Al, Bh, Bl), each 128 rows x 40 halves = 10240B
    constexpr uint32_t ARR = 10240u, STAGE = 40960u;

    const int tid  = threadIdx.x;
    const int warp = tid >> 5, lane = tid & 31;
    const int wm = warp >> 2, wn = warp & 3;     // 2 x 4 warp grid -> 64x32
    const int bz = blockIdx.z;
    const int m0 = blockIdx.y * 128, n0 = blockIdx.x * 128;

    const bf16* Ah = Ahg + (size_t)bz * sA + (size_t)m0 * K;
    const bf16* Al = Alg + (size_t)bz * sA + (size_t)m0 * K;
    const bf16* Bh = Bhg + (size_t)bz * sB + (size_t)n0 * K;
    const bf16* Bl = Blg + (size_t)bz * sB + (size_t)n0 * K;

    // ldmatrix lane decomposition
    const int rowA_l = lane & 15;                       // row within m16 block
    const int kA_l   = ((lane >> 4) & 1) * 8;           // +8 k for matrices 2,3
    const int rowB_l = (lane & 7) + ((lane & 16) >> 1); // row within n16 pair
    const int kB_l   = lane & 8;                        // +8 k for matrices 1,3

    float acc[4][4][4];
#pragma unroll
    for (int mt = 0; mt < 4; mt++)
#pragma unroll
        for (int nt = 0; nt < 4; nt++)
#pragma unroll
            for (int c = 0; c < 4; c++) acc[mt][nt][c] = 0.0f;

    const int NC = K >> 5;   // 32-half chunks

    // cp.async one stage: per array 128 rows x 2 x 16B units; 8 CP16/thread
#define ISSUE(stg, kk) do {                                                  \
        uint32_t sb_ = smem0 + (uint32_t)(stg) * STAGE;                      \
        _Pragma("unroll")                                                    \
        for (int j_ = 0; j_ < 2; j_++) {                                     \
            int idx_ = j_ * 256 + tid;                                       \
            int r_ = idx_ >> 2, u_ = idx_ & 3;                               \
            uint32_t off_ = (uint32_t)(r_ * 80 + u_ * 16);                   \
            size_t go_ = (size_t)r_ * K + (kk) + u_ * 8;                     \
            CP16(sb_ +            off_, Ah + go_);                           \
            CP16(sb_ +     ARR +  off_, Al + go_);                           \
            CP16(sb_ + 2 * ARR +  off_, Bh + go_);                           \
            CP16(sb_ + 3 * ARR +  off_, Bl + go_);                           \
        }                                                                    \
        CP_COMMIT();                                                         \
    } while (0)

    ISSUE(0, 0);

    for (int i = 0; i < NC; i++) {
        const int st = i & 1;
        const bool more = (i + 1) < NC;
        if (more) { ISSUE(st ^ 1, (i + 1) << 5); CP_WAIT1(); }
        else      { CP_WAIT0(); }
        __syncthreads();

        const uint32_t sb  = smem0 + (uint32_t)st * STAGE;
        const uint32_t sAh = sb, sAl = sb + ARR, sBh = sb + 2*ARR, sBl = sb + 3*ARR;

#pragma unroll
        for (int ks = 0; ks < 2; ks++) {
            // B fragments for all 4 nt (two n16 pairs), hi and lo
            uint32_t bh[4][2], bl[4][2];
            const uint32_t bo0 = (uint32_t)(((wn*32 +      rowB_l) * 40 + ks*16 + kB_l) << 1);
            const uint32_t bo1 = (uint32_t)(((wn*32 + 16 + rowB_l) * 40 + ks*16 + kB_l) << 1);
            LDSM_X4(bh[0][0], bh[0][1], bh[1][0], bh[1][1], sBh + bo0);
            LDSM_X4(bh[2][0], bh[2][1], bh[3][0], bh[3][1], sBh + bo1);
            LDSM_X4(bl[0][0], bl[0][1], bl[1][0], bl[1][1], sBl + bo0);
            LDSM_X4(bl[2][0], bl[2][1], bl[3][0], bl[3][1], sBl + bo1);

#pragma unroll
            for (int mt = 0; mt < 4; mt++) {
                const uint32_t ao =
                    (uint32_t)(((wm*64 + mt*16 + rowA_l) * 40 + ks*16 + kA_l) << 1);
                uint32_t ah[4], al[4];
                LDSM_X4(ah[0], ah[1], ah[2], ah[3], sAh + ao);
                LDSM_X4(al[0], al[1], al[2], al[3], sAl + ao);
#pragma unroll
                for (int nt = 0; nt < 4; nt++) {
                    MMA_BF16(acc[mt][nt], ah, bh[nt]);
                    MMA_BF16(acc[mt][nt], ah, bl[nt]);
                    MMA_BF16(acc[mt][nt], al, bh[nt]);
                }
            }
        }
        __syncthreads();
    }
#undef ISSUE

    // ---------------- epilogue ----------------
    const int g = lane >> 2, tq = lane & 3;
    unsigned mok0[4], mok1[4];
    if (EPI == 1) {
        const unsigned int* mk = maskg + (size_t)bz * sMask;
#pragma unroll
        for (int nt = 0; nt < 4; nt++) {
            const int col = n0 + wn * 32 + nt * 8 + tq * 2;
            mok0[nt] = mk[col];
            mok1[nt] = mk[col + 1];
        }
    }
    float* Cf = (EPI <= 1) ? Cfg + (size_t)bz * sC : nullptr;
    bf16*  Ch = (EPI == 2) ? Chg + (size_t)bz * sC : nullptr;
    bf16*  Cl = (EPI == 2) ? Clg + (size_t)bz * sC : nullptr;

#pragma unroll
    for (int mt = 0; mt < 4; mt++) {
        const int r0 = m0 + wm * 64 + mt * 16 + g;
#pragma unroll
        for (int nt = 0; nt < 4; nt++) {
            const int col = n0 + wn * 32 + nt * 8 + tq * 2;
            float c0 = acc[mt][nt][0], c1 = acc[mt][nt][1];
            float c2 = acc[mt][nt][2], c3 = acc[mt][nt][3];
            if (EPI == 1) {
                if (!mok0[nt]) { c0 = MASK_FILL_V; c2 = MASK_FILL_V; }
                if (!mok1[nt]) { c1 = MASK_FILL_V; c3 = MASK_FILL_V; }
            }
            if (EPI <= 1) {
                *(float2*)(Cf + (size_t)r0 * N + col)       = make_float2(c0, c1);
                *(float2*)(Cf + (size_t)(r0 + 8) * N + col) = make_float2(c2, c3);
            } else {
                bf16 h0,h1,h2,h3,l0,l1,l2,l3;
                split2(c0,h0,l0); split2(c1,h1,l1); split2(c2,h2,l2); split2(c3,h3,l3);
                __nv_bfloat162 t;
                t.x=h0; t.y=h1; *(__nv_bfloat162*)(Ch + (size_t)r0*N + col)     = t;
                t.x=h2; t.y=h3; *(__nv_bfloat162*)(Ch + (size_t)(r0+8)*N + col) = t;
                t.x=l0; t.y=l1; *(__nv_bfloat162*)(Cl + (size_t)r0*N + col)     = t;
                t.x=l2; t.y=l3; *(__nv_bfloat162*)(Cl + (size_t)(r0+8)*N + col) = t;
            }
        }
    }
}

// ---------------------------------------------------------------------------
// Row softmax over contiguous length-2048 rows of scores [b,t,s]; writes
// probabilities as (hi, lo) bf16 for the final tensor-core GEMM.
// ---------------------------------------------------------------------------
__global__ __launch_bounds__(256)
void softmax_rows(const float* __restrict__ scores,
                  bf16* __restrict__ ph, bf16* __restrict__ pl)
{
    const int tid = threadIdx.x;
    const size_t base = (size_t)blockIdx.x * SEQ1;
    const float* row = scores + base;

    float v[8];
    float mx = -3.4e38f;
#pragma unroll
    for (int i = 0; i < 8; i++) {
        v[i] = row[tid + (i << 8)];
        mx = fmaxf(mx, v[i]);
    }
#pragma unroll
    for (int o = 16; o > 0; o >>= 1)
        mx = fmaxf(mx, __shfl_xor_sync(0xffffffffu, mx, o));

    __shared__ float smax[8];
    __shared__ float ssum[8];
    if ((tid & 31) == 0) smax[tid >> 5] = mx;
    __syncthreads();
    mx = smax[0];
#pragma unroll
    for (int w = 1; w < 8; w++) mx = fmaxf(mx, smax[w]);

    float s = 0.0f;
#pragma unroll
    for (int i = 0; i < 8; i++) {
        v[i] = __expf(v[i] - mx);
        s += v[i];
    }
#pragma unroll
    for (int o = 16; o > 0; o >>= 1)
        s += __shfl_xor_sync(0xffffffffu, s, o);
    if ((tid & 31) == 0) ssum[tid >> 5] = s;
    __syncthreads();
    s = ssum[0];
#pragma unroll
    for (int w = 1; w < 8; w++) s += ssum[w];

    const float inv = 1.0f / s;
#pragma unroll
    for (int i = 0; i < 8; i++) {
        const float p = v[i] * inv;
        const size_t idx = base + tid + (i << 8);
        bf16 h, l; split2(p, h, l);
        ph[idx] = h; pl[idx] = l;
    }
}

// ---------------------------------------------------------------------------
extern "C" void kernel_launch(void* const* d_in, const int* in_sizes, int n_in,
                              void* d_out, int out_size)
{
    const float*        input1 = (const float*)d_in[0];          // [B,S1,D]
    const float*        input2 = (const float*)d_in[1];          // [B,S2,D]
    const unsigned int* mask   = (const unsigned int*)d_in[2];   // [B,S1] words
    const float*        weight = (const float*)d_in[3];          // [D,D]
    float*              out    = (float*)d_out;                  // [B,S2,D]

    bf16 *in1h,*in1l,*in2h,*in2l,*wh,*wl,*o1h,*o1l,*t1h,*t1l,*ph,*pl;
    float *scoresp;
    cudaGetSymbolAddress((void**)&in1h, g_in1h);
    cudaGetSymbolAddress((void**)&in1l, g_in1l);
    cudaGetSymbolAddress((void**)&in2h, g_in2h);
    cudaGetSymbolAddress((void**)&in2l, g_in2l);
    cudaGetSymbolAddress((void**)&wh,  g_wh);
    cudaGetSymbolAddress((void**)&wl,  g_wl);
    cudaGetSymbolAddress((void**)&o1h, g_o1h);
    cudaGetSymbolAddress((void**)&o1l, g_o1l);
    cudaGetSymbolAddress((void**)&t1h, g_t1h);
    cudaGetSymbolAddress((void**)&t1l, g_t1l);
    cudaGetSymbolAddress((void**)&ph,  g_ph);
    cudaGetSymbolAddress((void**)&pl,  g_pl);
    cudaGetSymbolAddress((void**)&scoresp, g_scores);

    const int SMEM_BYTES = 81920;   // 2 stages x 4 arrays x 10240B
    cudaFuncSetAttribute(gemm_mma<0>, cudaFuncAttributeMaxDynamicSharedMemorySize, SMEM_BYTES);
    cudaFuncSetAttribute(gemm_mma<1>, cudaFuncAttributeMaxDynamicSharedMemorySize, SMEM_BYTES);
    cudaFuncSetAttribute(gemm_mma<2>, cudaFuncAttributeMaxDynamicSharedMemorySize, SMEM_BYTES);

    const size_t n1 = (size_t)BATCH * SEQ1 * DIM;

    // 0) splits + transpose-split of input1
    split_kernel<<<(unsigned)(n1 / 1024), 256>>>(input1, in1h, in1l);
    split_kernel<<<(unsigned)(n1 / 1024), 256>>>(input2, in2h, in2l);
    split_kernel<<<(unsigned)((size_t)DIM * DIM / 1024), 256>>>(weight, wh, wl);
    transpose_split<<<dim3(SEQ1 / 32, DIM / 32, BATCH), 256>>>(input1, t1h, t1l);

    // 1) out1 = input1 @ weight^T  (NT, split bf16 out)
    gemm_mma<2><<<dim3(DIM / 128, (BATCH * SEQ1) / 128, 1), 256, SMEM_BYTES>>>(
        in1h, in1l, wh, wl, nullptr, o1h, o1l, nullptr,
        BATCH * SEQ1, DIM, DIM, 0, 0, 0, 0);

    // 2) scoresT[b,t,s] = input2[b,t,:] . out1[b,s,:]  (batched NT, mask on s)
    gemm_mma<1><<<dim3(SEQ1 / 128, SEQ2 / 128, BATCH), 256, SMEM_BYTES>>>(
        in2h, in2l, o1h, o1l, scoresp, nullptr, nullptr, mask,
        SEQ2, SEQ1, DIM,
        (size_t)SEQ2 * DIM, (size_t)SEQ1 * DIM, (size_t)SEQ2 * SEQ1, (size_t)SEQ1);

    // 3) softmax over s + split probabilities
    softmax_rows<<<BATCH * SEQ2, 256>>>(scoresp, ph, pl);

    // 4) out[b,t,d] = sum_s P[b,t,s] * input1[b,s,d]  (NT vs input1^T, fp32 out)
    gemm_mma<0><<<dim3(DIM / 128, SEQ2 / 128, BATCH), 256, SMEM_BYTES>>>(
        ph, pl, t1h, t1l, out, nullptr, nullptr, nullptr,
        SEQ2, DIM, SEQ1,
        (size_t)SEQ2 * SEQ1, (size_t)DIM * SEQ1, (size_t)SEQ2 * DIM, 0);
}

// round 6
// speedup vs baseline: 1.2641x; 1.2641x over previous
#include <cuda_runtime.h>
#include <cuda_bf16.h>
#include <stdint.h>

#define BATCH 8
#define SEQ1  2048
#define SEQ2  2048
#define DIM   1024
#define MASK_FILL_V (-100.0f)

using bf16 = __nv_bfloat16;

// ---------------- scratch (static __device__, no allocation) ----------------
__device__ bf16  g_in1h[(size_t)BATCH*SEQ1*DIM];
__device__ bf16  g_in1l[(size_t)BATCH*SEQ1*DIM];
__device__ bf16  g_in2h[(size_t)BATCH*SEQ2*DIM];
__device__ bf16  g_in2l[(size_t)BATCH*SEQ2*DIM];
__device__ bf16  g_wh[(size_t)DIM*DIM];
__device__ bf16  g_wl[(size_t)DIM*DIM];
__device__ bf16  g_o1h[(size_t)BATCH*SEQ1*DIM];
__device__ bf16  g_o1l[(size_t)BATCH*SEQ1*DIM];
__device__ bf16  g_t1h[(size_t)BATCH*DIM*SEQ1];   // input1^T split [B,D,S1]
__device__ bf16  g_t1l[(size_t)BATCH*DIM*SEQ1];
__device__ float g_scores[(size_t)BATCH*SEQ2*SEQ1];
__device__ bf16  g_ph[(size_t)BATCH*SEQ2*SEQ1];
__device__ bf16  g_pl[(size_t)BATCH*SEQ2*SEQ1];

__device__ __forceinline__ void split2(float x, bf16 &h, bf16 &l) {
    h = __float2bfloat16(x);
    l = __float2bfloat16(x - __bfloat162float(h));
}

// ---------------- small helper kernels ----------------
__global__ __launch_bounds__(256) void split_kernel(const float* __restrict__ x,
                                                    bf16* __restrict__ h,
                                                    bf16* __restrict__ l) {
    size_t i = ((size_t)blockIdx.x * 256 + threadIdx.x) * 4;
    float4 v = *(const float4*)(x + i);
    bf16 h0,h1,h2,h3,l0,l1,l2,l3;
    split2(v.x,h0,l0); split2(v.y,h1,l1); split2(v.z,h2,l2); split2(v.w,h3,l3);
    __nv_bfloat162 a, b;
    a.x=h0; a.y=h1; b.x=h2; b.y=h3;
    ((__nv_bfloat162*)(h+i))[0] = a; ((__nv_bfloat162*)(h+i))[1] = b;
    a.x=l0; a.y=l1; b.x=l2; b.y=l3;
    ((__nv_bfloat162*)(l+i))[0] = a; ((__nv_bfloat162*)(l+i))[1] = b;
}

// input1 [B,S1,D] fp32 -> transposed split [B,D,S1] bf16 hi/lo
__global__ __launch_bounds__(256)
void transpose_split(const float* __restrict__ x, bf16* __restrict__ th,
                     bf16* __restrict__ tl) {
    __shared__ float t[32][33];
    const int b  = blockIdx.z;
    const int s0 = blockIdx.x * 32, d0 = blockIdx.y * 32;
    const int tx = threadIdx.x & 31, ty = threadIdx.x >> 5;   // 8 rows/pass
    const float* xp = x + ((size_t)b * SEQ1 + s0) * DIM + d0;
#pragma unroll
    for (int k = 0; k < 4; k++)
        t[ty + 8*k][tx] = xp[(size_t)(ty + 8*k) * DIM + tx];
    __syncthreads();
    const size_t ob = ((size_t)b * DIM + d0) * SEQ1 + s0;
#pragma unroll
    for (int k = 0; k < 4; k++) {
        bf16 h, l; split2(t[tx][ty + 8*k], h, l);
        th[ob + (size_t)(ty + 8*k) * SEQ1 + tx] = h;
        tl[ob + (size_t)(ty + 8*k) * SEQ1 + tx] = l;
    }
}

// ---------------- PTX helpers ----------------
#define CP16(dst, src) asm volatile("cp.async.cg.shared.global [%0], [%1], 16;\n" :: "r"(dst), "l"(src))
#define CP_COMMIT()    asm volatile("cp.async.commit_group;\n")
#define CP_WAIT1()     asm volatile("cp.async.wait_group 1;\n")
#define CP_WAIT0()     asm volatile("cp.async.wait_group 0;\n")

#define MMA_BF16(d, a, b) asm volatile( \
  "mma.sync.aligned.m16n8k16.row.col.f32.bf16.bf16.f32 " \
  "{%0,%1,%2,%3},{%4,%5,%6,%7},{%8,%9},{%0,%1,%2,%3};\n" \
  : "+f"(d[0]), "+f"(d[1]), "+f"(d[2]), "+f"(d[3]) \
  : "r"(a[0]), "r"(a[1]), "r"(a[2]), "r"(a[3]), "r"(b[0]), "r"(b[1]))

// ---------------------------------------------------------------------------
// Split-bf16 HMMA NT GEMM: C[M,N] = A[M,K]*B[N,K]^T, 3-product split
// (C += Ah*Bh + Ah*Bl + Al*Bh). 128x128 tile, BK=16, 256 threads (8 warps,
// warp tile 64x32), 3-stage cp.async pipeline with ONE __syncthreads per
// chunk. smem rows stride 24 halves; fragment loads via 32-bit LDS using the
// m16n8k16 thread mapping (proven in round 3). Products issued product-major
// per mt so same-accumulator MMAs are 4 apart (breaks RAW chains).
//   EPI=0: fp32 out.  EPI=1: fp32 out + column(N) mask.  EPI=2: split bf16 out.
// ---------------------------------------------------------------------------
template<int EPI>
__global__ __launch_bounds__(256, 2)
void gemm_mma(const bf16* __restrict__ Ahg, const bf16* __restrict__ Alg,
              const bf16* __restrict__ Bhg, const bf16* __restrict__ Blg,
              float* __restrict__ Cfg, bf16* __restrict__ Chg, bf16* __restrict__ Clg,
              const unsigned int* __restrict__ maskg,
              int M, int N, int K,
              size_t sA, size_t sB, size_t sC, size_t sMask)
{
    extern __shared__ __align__(16) char dsm[];
    const uint32_t smem0 = (uint32_t)__cvta_generic_to_shared(dsm);
    constexpr uint32_t ARR = 6144u;      // 128 rows x 24 halves x 2B
    constexpr uint32_t STAGE = 4u * ARR; // 24576B; 3 stages = 73728B

    const int tid  = threadIdx.x;
    const int warp = tid >> 5, lane = tid & 31;
    const int wm = warp >> 2, wn = warp & 3;     // 2 x 4 warp grid -> 64x32
    const int g  = lane >> 2, tq = lane & 3;
    const int bz = blockIdx.z;
    const int m0 = blockIdx.y * 128, n0 = blockIdx.x * 128;

    const bf16* Ah = Ahg + (size_t)bz * sA + (size_t)m0 * K;
    const bf16* Al = Alg + (size_t)bz * sA + (size_t)m0 * K;
    const bf16* Bh = Bhg + (size_t)bz * sB + (size_t)n0 * K;
    const bf16* Bl = Blg + (size_t)bz * sB + (size_t)n0 * K;

    // per-thread cp.async source/dest (1 x 16B per array per chunk)
    const int r_ = tid >> 1, u_ = tid & 1;
    const uint32_t offc = (uint32_t)(r_ * 48 + u_ * 16);

    float acc[4][4][4];
#pragma unroll
    for (int mt = 0; mt < 4; mt++)
#pragma unroll
        for (int nt = 0; nt < 4; nt++)
#pragma unroll
            for (int c = 0; c < 4; c++) acc[mt][nt][c] = 0.0f;

    const int NC = K >> 4;   // 16-half chunks

#define ISSUE(stg, kk) do {                                                  \
        uint32_t sb_ = smem0 + (uint32_t)(stg) * STAGE;                      \
        size_t go_ = (size_t)r_ * K + (kk) + u_ * 8;                         \
        CP16(sb_ +           offc, Ah + go_);                                \
        CP16(sb_ +    ARR +  offc, Al + go_);                                \
        CP16(sb_ + 2u*ARR +  offc, Bh + go_);                                \
        CP16(sb_ + 3u*ARR +  offc, Bl + go_);                                \
        CP_COMMIT();                                                         \
    } while (0)

    ISSUE(0, 0);
    ISSUE(1, 16);

    for (int i = 0; i < NC; i++) {
        if (i + 1 < NC) { CP_WAIT1(); } else { CP_WAIT0(); }
        __syncthreads();
        if (i + 2 < NC) ISSUE((i + 2) % 3, (i + 2) << 4);

        const bf16* st = (const bf16*)(dsm + (size_t)(i % 3) * STAGE);
        const bf16* As_h = st;
        const bf16* As_l = st + ARR / 2;
        const bf16* Bs_h = st + ARR;
        const bf16* Bs_l = st + 3 * (ARR / 2);

        // B fragments: all 4 nt, hi and lo
        uint32_t bh[4][2], bl[4][2];
#pragma unroll
        for (int nt = 0; nt < 4; nt++) {
            const int b0 = (wn * 32 + nt * 8 + g) * 24 + tq * 2;
            bh[nt][0] = *(const uint32_t*)(Bs_h + b0);
            bh[nt][1] = *(const uint32_t*)(Bs_h + b0 + 8);
            bl[nt][0] = *(const uint32_t*)(Bs_l + b0);
            bl[nt][1] = *(const uint32_t*)(Bs_l + b0 + 8);
        }
#pragma unroll
        for (int mt = 0; mt < 4; mt++) {
            const int a0 = (wm * 64 + mt * 16 + g) * 24 + tq * 2;
            uint32_t ah[4], al[4];
            ah[0] = *(const uint32_t*)(As_h + a0);
            ah[1] = *(const uint32_t*)(As_h + a0 + 8*24);
            ah[2] = *(const uint32_t*)(As_h + a0 + 8);
            ah[3] = *(const uint32_t*)(As_h + a0 + 8*24 + 8);
            al[0] = *(const uint32_t*)(As_l + a0);
            al[1] = *(const uint32_t*)(As_l + a0 + 8*24);
            al[2] = *(const uint32_t*)(As_l + a0 + 8);
            al[3] = *(const uint32_t*)(As_l + a0 + 8*24 + 8);
            // product-major: same-acc MMAs are 4 apart
#pragma unroll
            for (int nt = 0; nt < 4; nt++) MMA_BF16(acc[mt][nt], ah, bh[nt]);
#pragma unroll
            for (int nt = 0; nt < 4; nt++) MMA_BF16(acc[mt][nt], ah, bl[nt]);
#pragma unroll
            for (int nt = 0; nt < 4; nt++) MMA_BF16(acc[mt][nt], al, bh[nt]);
        }
    }
#undef ISSUE

    // ---------------- epilogue ----------------
    unsigned mok0[4], mok1[4];
    if (EPI == 1) {
        const unsigned int* mk = maskg + (size_t)bz * sMask;
#pragma unroll
        for (int nt = 0; nt < 4; nt++) {
            const int col = n0 + wn * 32 + nt * 8 + tq * 2;
            mok0[nt] = mk[col];
            mok1[nt] = mk[col + 1];
        }
    }
    float* Cf = (EPI <= 1) ? Cfg + (size_t)bz * sC : nullptr;
    bf16*  Ch = (EPI == 2) ? Chg + (size_t)bz * sC : nullptr;
    bf16*  Cl = (EPI == 2) ? Clg + (size_t)bz * sC : nullptr;

#pragma unroll
    for (int mt = 0; mt < 4; mt++) {
        const int r0 = m0 + wm * 64 + mt * 16 + g;
#pragma unroll
        for (int nt = 0; nt < 4; nt++) {
            const int col = n0 + wn * 32 + nt * 8 + tq * 2;
            float c0 = acc[mt][nt][0], c1 = acc[mt][nt][1];
            float c2 = acc[mt][nt][2], c3 = acc[mt][nt][3];
            if (EPI == 1) {
                if (!mok0[nt]) { c0 = MASK_FILL_V; c2 = MASK_FILL_V; }
                if (!mok1[nt]) { c1 = MASK_FILL_V; c3 = MASK_FILL_V; }
            }
            if (EPI <= 1) {
                *(float2*)(Cf + (size_t)r0 * N + col)       = make_float2(c0, c1);
                *(float2*)(Cf + (size_t)(r0 + 8) * N + col) = make_float2(c2, c3);
            } else {
                bf16 h0,h1,h2,h3,l0,l1,l2,l3;
                split2(c0,h0,l0); split2(c1,h1,l1); split2(c2,h2,l2); split2(c3,h3,l3);
                __nv_bfloat162 t;
                t.x=h0; t.y=h1; *(__nv_bfloat162*)(Ch + (size_t)r0*N + col)     = t;
                t.x=h2; t.y=h3; *(__nv_bfloat162*)(Ch + (size_t)(r0+8)*N + col) = t;
                t.x=l0; t.y=l1; *(__nv_bfloat162*)(Cl + (size_t)r0*N + col)     = t;
                t.x=l2; t.y=l3; *(__nv_bfloat162*)(Cl + (size_t)(r0+8)*N + col) = t;
            }
        }
    }
}

// ---------------------------------------------------------------------------
// Row softmax over contiguous length-2048 rows of scores [b,t,s]; writes
// probabilities as (hi, lo) bf16 for the final tensor-core GEMM.
// ---------------------------------------------------------------------------
__global__ __launch_bounds__(256)
void softmax_rows(const float* __restrict__ scores,
                  bf16* __restrict__ ph, bf16* __restrict__ pl)
{
    const int tid = threadIdx.x;
    const size_t base = (size_t)blockIdx.x * SEQ1;
    const float* row = scores + base;

    float v[8];
    float mx = -3.4e38f;
#pragma unroll
    for (int i = 0; i < 8; i++) {
        v[i] = row[tid + (i << 8)];
        mx = fmaxf(mx, v[i]);
    }
#pragma unroll
    for (int o = 16; o > 0; o >>= 1)
        mx = fmaxf(mx, __shfl_xor_sync(0xffffffffu, mx, o));

    __shared__ float smax[8];
    __shared__ float ssum[8];
    if ((tid & 31) == 0) smax[tid >> 5] = mx;
    __syncthreads();
    mx = smax[0];
#pragma unroll
    for (int w = 1; w < 8; w++) mx = fmaxf(mx, smax[w]);

    float s = 0.0f;
#pragma unroll
    for (int i = 0; i < 8; i++) {
        v[i] = __expf(v[i] - mx);
        s += v[i];
    }
#pragma unroll
    for (int o = 16; o > 0; o >>= 1)
        s += __shfl_xor_sync(0xffffffffu, s, o);
    if ((tid & 31) == 0) ssum[tid >> 5] = s;
    __syncthreads();
    s = ssum[0];
#pragma unroll
    for (int w = 1; w < 8; w++) s += ssum[w];

    const float inv = 1.0f / s;
#pragma unroll
    for (int i = 0; i < 8; i++) {
        const float p = v[i] * inv;
        const size_t idx = base + tid + (i << 8);
        bf16 h, l; split2(p, h, l);
        ph[idx] = h; pl[idx] = l;
    }
}

// ---------------------------------------------------------------------------
extern "C" void kernel_launch(void* const* d_in, const int* in_sizes, int n_in,
                              void* d_out, int out_size)
{
    const float*        input1 = (const float*)d_in[0];          // [B,S1,D]
    const float*        input2 = (const float*)d_in[1];          // [B,S2,D]
    const unsigned int* mask   = (const unsigned int*)d_in[2];   // [B,S1] words
    const float*        weight = (const float*)d_in[3];          // [D,D]
    float*              out    = (float*)d_out;                  // [B,S2,D]

    bf16 *in1h,*in1l,*in2h,*in2l,*wh,*wl,*o1h,*o1l,*t1h,*t1l,*ph,*pl;
    float *scoresp;
    cudaGetSymbolAddress((void**)&in1h, g_in1h);
    cudaGetSymbolAddress((void**)&in1l, g_in1l);
    cudaGetSymbolAddress((void**)&in2h, g_in2h);
    cudaGetSymbolAddress((void**)&in2l, g_in2l);
    cudaGetSymbolAddress((void**)&wh,  g_wh);
    cudaGetSymbolAddress((void**)&wl,  g_wl);
    cudaGetSymbolAddress((void**)&o1h, g_o1h);
    cudaGetSymbolAddress((void**)&o1l, g_o1l);
    cudaGetSymbolAddress((void**)&t1h, g_t1h);
    cudaGetSymbolAddress((void**)&t1l, g_t1l);
    cudaGetSymbolAddress((void**)&ph,  g_ph);
    cudaGetSymbolAddress((void**)&pl,  g_pl);
    cudaGetSymbolAddress((void**)&scoresp, g_scores);

    const int SMEM_BYTES = 73728;   // 3 stages x 4 arrays x 6144B
    cudaFuncSetAttribute(gemm_mma<0>, cudaFuncAttributeMaxDynamicSharedMemorySize, SMEM_BYTES);
    cudaFuncSetAttribute(gemm_mma<1>, cudaFuncAttributeMaxDynamicSharedMemorySize, SMEM_BYTES);
    cudaFuncSetAttribute(gemm_mma<2>, cudaFuncAttributeMaxDynamicSharedMemorySize, SMEM_BYTES);

    const size_t n1 = (size_t)BATCH * SEQ1 * DIM;

    // 0) splits + transpose-split of input1
    split_kernel<<<(unsigned)(n1 / 1024), 256>>>(input1, in1h, in1l);
    split_kernel<<<(unsigned)(n1 / 1024), 256>>>(input2, in2h, in2l);
    split_kernel<<<(unsigned)((size_t)DIM * DIM / 1024), 256>>>(weight, wh, wl);
    transpose_split<<<dim3(SEQ1 / 32, DIM / 32, BATCH), 256>>>(input1, t1h, t1l);

    // 1) out1 = input1 @ weight^T  (NT, split bf16 out)
    gemm_mma<2><<<dim3(DIM / 128, (BATCH * SEQ1) / 128, 1), 256, SMEM_BYTES>>>(
        in1h, in1l, wh, wl, nullptr, o1h, o1l, nullptr,
        BATCH * SEQ1, DIM, DIM, 0, 0, 0, 0);

    // 2) scoresT[b,t,s] = input2[b,t,:] . out1[b,s,:]  (batched NT, mask on s)
    gemm_mma<1><<<dim3(SEQ1 / 128, SEQ2 / 128, BATCH), 256, SMEM_BYTES>>>(
        in2h, in2l, o1h, o1l, scoresp, nullptr, nullptr, mask,
        SEQ2, SEQ1, DIM,
        (size_t)SEQ2 * DIM, (size_t)SEQ1 * DIM, (size_t)SEQ2 * SEQ1, (size_t)SEQ1);

    // 3) softmax over s + split probabilities
    softmax_rows<<<BATCH * SEQ2, 256>>>(scoresp, ph, pl);

    // 4) out[b,t,d] = sum_s P[b,t,s] * input1[b,s,d]  (NT vs input1^T, fp32 out)
    gemm_mma<0><<<dim3(DIM / 128, SEQ2 / 128, BATCH), 256, SMEM_BYTES>>>(
        ph, pl, t1h, t1l, out, nullptr, nullptr, nullptr,
        SEQ2, DIM, SEQ1,
        (size_t)SEQ2 * SEQ1, (size_t)DIM * SEQ1, (size_t)SEQ2 * DIM, 0);
}

// round 7
// speedup vs baseline: 1.3151x; 1.0404x over previous
#include <cuda_runtime.h>
#include <cuda_bf16.h>
#include <stdint.h>

#define BATCH 8
#define SEQ1  2048
#define SEQ2  2048
#define DIM   1024
#define MASK_FILL_V (-100.0f)

using bf16 = __nv_bfloat16;

// ---------------- scratch (static __device__, no allocation) ----------------
__device__ bf16  g_in1h[(size_t)BATCH*SEQ1*DIM];
__device__ bf16  g_in1l[(size_t)BATCH*SEQ1*DIM];
__device__ bf16  g_in2h[(size_t)BATCH*SEQ2*DIM];
__device__ bf16  g_in2l[(size_t)BATCH*SEQ2*DIM];
__device__ bf16  g_wh[(size_t)DIM*DIM];
__device__ bf16  g_wl[(size_t)DIM*DIM];
__device__ bf16  g_o1h[(size_t)BATCH*SEQ1*DIM];
__device__ bf16  g_o1l[(size_t)BATCH*SEQ1*DIM];
__device__ bf16  g_t1h[(size_t)BATCH*DIM*SEQ1];   // input1^T split [B,D,S1]
__device__ bf16  g_t1l[(size_t)BATCH*DIM*SEQ1];
__device__ float g_scores[(size_t)BATCH*SEQ2*SEQ1];
__device__ bf16  g_ph[(size_t)BATCH*SEQ2*SEQ1];
__device__ bf16  g_pl[(size_t)BATCH*SEQ2*SEQ1];

__device__ __forceinline__ void split2(float x, bf16 &h, bf16 &l) {
    h = __float2bfloat16(x);
    l = __float2bfloat16(x - __bfloat162float(h));
}

// ---------------- small helper kernels ----------------
__global__ __launch_bounds__(256) void split_kernel(const float* __restrict__ x,
                                                    bf16* __restrict__ h,
                                                    bf16* __restrict__ l) {
    size_t i = ((size_t)blockIdx.x * 256 + threadIdx.x) * 4;
    float4 v = *(const float4*)(x + i);
    bf16 h0,h1,h2,h3,l0,l1,l2,l3;
    split2(v.x,h0,l0); split2(v.y,h1,l1); split2(v.z,h2,l2); split2(v.w,h3,l3);
    __nv_bfloat162 a, b;
    a.x=h0; a.y=h1; b.x=h2; b.y=h3;
    ((__nv_bfloat162*)(h+i))[0] = a; ((__nv_bfloat162*)(h+i))[1] = b;
    a.x=l0; a.y=l1; b.x=l2; b.y=l3;
    ((__nv_bfloat162*)(l+i))[0] = a; ((__nv_bfloat162*)(l+i))[1] = b;
}

// input1 [B,S1,D] fp32 -> transposed split [B,D,S1] bf16 hi/lo
__global__ __launch_bounds__(256)
void transpose_split(const float* __restrict__ x, bf16* __restrict__ th,
                     bf16* __restrict__ tl) {
    __shared__ float t[32][33];
    const int b  = blockIdx.z;
    const int s0 = blockIdx.x * 32, d0 = blockIdx.y * 32;
    const int tx = threadIdx.x & 31, ty = threadIdx.x >> 5;   // 8 rows/pass
    const float* xp = x + ((size_t)b * SEQ1 + s0) * DIM + d0;
#pragma unroll
    for (int k = 0; k < 4; k++)
        t[ty + 8*k][tx] = xp[(size_t)(ty + 8*k) * DIM + tx];
    __syncthreads();
    const size_t ob = ((size_t)b * DIM + d0) * SEQ1 + s0;
#pragma unroll
    for (int k = 0; k < 4; k++) {
        bf16 h, l; split2(t[tx][ty + 8*k], h, l);
        th[ob + (size_t)(ty + 8*k) * SEQ1 + tx] = h;
        tl[ob + (size_t)(ty + 8*k) * SEQ1 + tx] = l;
    }
}

// ---------------- PTX helpers ----------------
#define CP16(dst, src) asm volatile("cp.async.cg.shared.global [%0], [%1], 16;\n" :: "r"(dst), "l"(src))
#define CP_COMMIT()    asm volatile("cp.async.commit_group;\n")
#define CP_WAIT1()     asm volatile("cp.async.wait_group 1;\n")
#define CP_WAIT0()     asm volatile("cp.async.wait_group 0;\n")

#define MMA_BF16(d, a, b) asm volatile( \
  "mma.sync.aligned.m16n8k16.row.col.f32.bf16.bf16.f32 " \
  "{%0,%1,%2,%3},{%4,%5,%6,%7},{%8,%9},{%0,%1,%2,%3};\n" \
  : "+f"(d[0]), "+f"(d[1]), "+f"(d[2]), "+f"(d[3]) \
  : "r"(a[0]), "r"(a[1]), "r"(a[2]), "r"(a[3]), "r"(b[0]), "r"(b[1]))

#define LDSM_X4(r0, r1, r2, r3, addr) asm volatile( \
  "ldmatrix.sync.aligned.m8n8.x4.shared.b16 {%0,%1,%2,%3}, [%4];\n" \
  : "=r"(r0), "=r"(r1), "=r"(r2), "=r"(r3) : "r"(addr))

// ---------------------------------------------------------------------------
// Split-bf16 HMMA NT GEMM: C[M,N] = A[M,K]*B[N,K]^T, 3-product split
// (C += Ah*Bh + Ah*Bl + Al*Bh). 128x128 tile, BK=16, 256 threads (8 warps,
// warp tile 64x32), 3-stage cp.async pipeline, ONE __syncthreads per chunk.
// smem rows stride 24 halves (48B) -> ldmatrix conflict-free (row banks
// {0,12,24,4,16,28,8,20}, disjoint 4-bank ranges). Fragments via ldmatrix.x4.
// Global product-major MMA order: same-acc reuse distance = 16 MMAs.
//   EPI=0: fp32 out.  EPI=1: fp32 out + column(N) mask.  EPI=2: split bf16 out.
// ---------------------------------------------------------------------------
template<int EPI>
__global__ __launch_bounds__(256, 2)
void gemm_mma(const bf16* __restrict__ Ahg, const bf16* __restrict__ Alg,
              const bf16* __restrict__ Bhg, const bf16* __restrict__ Blg,
              float* __restrict__ Cfg, bf16* __restrict__ Chg, bf16* __restrict__ Clg,
              const unsigned int* __restrict__ maskg,
              int M, int N, int K,
              size_t sA, size_t sB, size_t sC, size_t sMask)
{
    extern __shared__ __align__(16) char dsm[];
    const uint32_t smem0 = (uint32_t)__cvta_generic_to_shared(dsm);
    constexpr uint32_t ARR = 6144u;      // 128 rows x 24 halves x 2B
    constexpr uint32_t STAGE = 4u * ARR; // 24576B; 3 stages = 73728B

    const int tid  = threadIdx.x;
    const int warp = tid >> 5, lane = tid & 31;
    const int wm = warp >> 2, wn = warp & 3;     // 2 x 4 warp grid -> 64x32
    const int g  = lane >> 2, tq = lane & 3;
    const int bz = blockIdx.z;
    const int m0 = blockIdx.y * 128, n0 = blockIdx.x * 128;

    const bf16* Ah = Ahg + (size_t)bz * sA + (size_t)m0 * K;
    const bf16* Al = Alg + (size_t)bz * sA + (size_t)m0 * K;
    const bf16* Bh = Bhg + (size_t)bz * sB + (size_t)n0 * K;
    const bf16* Bl = Blg + (size_t)bz * sB + (size_t)n0 * K;

    // per-thread cp.async source/dest (1 x 16B per array per chunk)
    const int r_ = tid >> 1, u_ = tid & 1;
    const uint32_t offc = (uint32_t)(r_ * 48 + u_ * 16);

    // ldmatrix per-lane address components (bytes)
    // A: lanes 0-15 -> rows m0-15 @k0 ; lanes 16-31 -> rows m0-15 @k8
    const uint32_t aOff =
        (uint32_t)(((lane & 15) * 24 + ((lane >> 4) & 1) * 8) * 2);
    // B (per p covering nt=2p,2p+1): l0-7 n0-7@k0, l8-15 n0-7@k8,
    //                                l16-23 n8-15@k0, l24-31 n8-15@k8
    const uint32_t bOffL =
        (uint32_t)((((lane & 7) + ((lane >> 4) & 1) * 8) * 24 +
                    ((lane >> 3) & 1) * 8) * 2);

    float acc[4][4][4];
#pragma unroll
    for (int mt = 0; mt < 4; mt++)
#pragma unroll
        for (int nt = 0; nt < 4; nt++)
#pragma unroll
            for (int c = 0; c < 4; c++) acc[mt][nt][c] = 0.0f;

    const int NC = K >> 4;   // 16-half chunks

#define ISSUE(stg, kk) do {                                                  \
        uint32_t sb_ = smem0 + (uint32_t)(stg) * STAGE;                      \
        size_t go_ = (size_t)r_ * K + (kk) + u_ * 8;                         \
        CP16(sb_ +           offc, Ah + go_);                                \
        CP16(sb_ +    ARR +  offc, Al + go_);                                \
        CP16(sb_ + 2u*ARR +  offc, Bh + go_);                                \
        CP16(sb_ + 3u*ARR +  offc, Bl + go_);                                \
        CP_COMMIT();                                                         \
    } while (0)

    ISSUE(0, 0);
    ISSUE(1, 16);

    for (int i = 0; i < NC; i++) {
        if (i + 1 < NC) { CP_WAIT1(); } else { CP_WAIT0(); }
        __syncthreads();
        if (i + 2 < NC) ISSUE((i + 2) % 3, (i + 2) << 4);

        const uint32_t stb = smem0 + (uint32_t)(i % 3) * STAGE;

        // ---- B fragments: 2 ldmatrix.x4 per precision ----
        uint32_t bh4[2][4], bl4[2][4];
#pragma unroll
        for (int p = 0; p < 2; p++) {
            const uint32_t bo =
                stb + 2u * ARR + (uint32_t)((wn * 32 + p * 16) * 48) + bOffL;
            LDSM_X4(bh4[p][0], bh4[p][1], bh4[p][2], bh4[p][3], bo);
            LDSM_X4(bl4[p][0], bl4[p][1], bl4[p][2], bl4[p][3], bo + ARR);
        }
        // ---- A hi fragments: 4 ldmatrix.x4 ----
        uint32_t ah[4][4];
#pragma unroll
        for (int mt = 0; mt < 4; mt++) {
            const uint32_t ao =
                stb + (uint32_t)((wm * 64 + mt * 16) * 48) + aOff;
            LDSM_X4(ah[mt][0], ah[mt][1], ah[mt][2], ah[mt][3], ao);
        }

        // phase 1: Ah*Bh (16 MMAs, every acc once)
#pragma unroll
        for (int mt = 0; mt < 4; mt++)
#pragma unroll
            for (int nt = 0; nt < 4; nt++)
                MMA_BF16(acc[mt][nt], ah[mt], (&bh4[nt >> 1][(nt & 1) * 2]));
        // phase 2: Ah*Bl
#pragma unroll
        for (int mt = 0; mt < 4; mt++)
#pragma unroll
            for (int nt = 0; nt < 4; nt++)
                MMA_BF16(acc[mt][nt], ah[mt], (&bl4[nt >> 1][(nt & 1) * 2]));
        // phase 3: Al*Bh (load Al per mt)
#pragma unroll
        for (int mt = 0; mt < 4; mt++) {
            const uint32_t ao =
                stb + ARR + (uint32_t)((wm * 64 + mt * 16) * 48) + aOff;
            uint32_t al[4];
            LDSM_X4(al[0], al[1], al[2], al[3], ao);
#pragma unroll
            for (int nt = 0; nt < 4; nt++)
                MMA_BF16(acc[mt][nt], al, (&bh4[nt >> 1][(nt & 1) * 2]));
        }
    }
#undef ISSUE

    // ---------------- epilogue ----------------
    unsigned mok0[4], mok1[4];
    if (EPI == 1) {
        const unsigned int* mk = maskg + (size_t)bz * sMask;
#pragma unroll
        for (int nt = 0; nt < 4; nt++) {
            const int col = n0 + wn * 32 + nt * 8 + tq * 2;
            mok0[nt] = mk[col];
            mok1[nt] = mk[col + 1];
        }
    }
    float* Cf = (EPI <= 1) ? Cfg + (size_t)bz * sC : nullptr;
    bf16*  Ch = (EPI == 2) ? Chg + (size_t)bz * sC : nullptr;
    bf16*  Cl = (EPI == 2) ? Clg + (size_t)bz * sC : nullptr;

#pragma unroll
    for (int mt = 0; mt < 4; mt++) {
        const int r0 = m0 + wm * 64 + mt * 16 + g;
#pragma unroll
        for (int nt = 0; nt < 4; nt++) {
            const int col = n0 + wn * 32 + nt * 8 + tq * 2;
            float c0 = acc[mt][nt][0], c1 = acc[mt][nt][1];
            float c2 = acc[mt][nt][2], c3 = acc[mt][nt][3];
            if (EPI == 1) {
                if (!mok0[nt]) { c0 = MASK_FILL_V; c2 = MASK_FILL_V; }
                if (!mok1[nt]) { c1 = MASK_FILL_V; c3 = MASK_FILL_V; }
            }
            if (EPI <= 1) {
                *(float2*)(Cf + (size_t)r0 * N + col)       = make_float2(c0, c1);
                *(float2*)(Cf + (size_t)(r0 + 8) * N + col) = make_float2(c2, c3);
            } else {
                bf16 h0,h1,h2,h3,l0,l1,l2,l3;
                split2(c0,h0,l0); split2(c1,h1,l1); split2(c2,h2,l2); split2(c3,h3,l3);
                __nv_bfloat162 t;
                t.x=h0; t.y=h1; *(__nv_bfloat162*)(Ch + (size_t)r0*N + col)     = t;
                t.x=h2; t.y=h3; *(__nv_bfloat162*)(Ch + (size_t)(r0+8)*N + col) = t;
                t.x=l0; t.y=l1; *(__nv_bfloat162*)(Cl + (size_t)r0*N + col)     = t;
                t.x=l2; t.y=l3; *(__nv_bfloat162*)(Cl + (size_t)(r0+8)*N + col) = t;
            }
        }
    }
}

// ---------------------------------------------------------------------------
// Row softmax over contiguous length-2048 rows of scores [b,t,s]; writes
// probabilities as (hi, lo) bf16 for the final tensor-core GEMM.
// ---------------------------------------------------------------------------
__global__ __launch_bounds__(256)
void softmax_rows(const float* __restrict__ scores,
                  bf16* __restrict__ ph, bf16* __restrict__ pl)
{
    const int tid = threadIdx.x;
    const size_t base = (size_t)blockIdx.x * SEQ1;
    const float* row = scores + base;

    float v[8];
    float mx = -3.4e38f;
#pragma unroll
    for (int i = 0; i < 8; i++) {
        v[i] = row[tid + (i << 8)];
        mx = fmaxf(mx, v[i]);
    }
#pragma unroll
    for (int o = 16; o > 0; o >>= 1)
        mx = fmaxf(mx, __shfl_xor_sync(0xffffffffu, mx, o));

    __shared__ float smax[8];
    __shared__ float ssum[8];
    if ((tid & 31) == 0) smax[tid >> 5] = mx;
    __syncthreads();
    mx = smax[0];
#pragma unroll
    for (int w = 1; w < 8; w++) mx = fmaxf(mx, smax[w]);

    float s = 0.0f;
#pragma unroll
    for (int i = 0; i < 8; i++) {
        v[i] = __expf(v[i] - mx);
        s += v[i];
    }
#pragma unroll
    for (int o = 16; o > 0; o >>= 1)
        s += __shfl_xor_sync(0xffffffffu, s, o);
    if ((tid & 31) == 0) ssum[tid >> 5] = s;
    __syncthreads();
    s = ssum[0];
#pragma unroll
    for (int w = 1; w < 8; w++) s += ssum[w];

    const float inv = 1.0f / s;
#pragma unroll
    for (int i = 0; i < 8; i++) {
        const float p = v[i] * inv;
        const size_t idx = base + tid + (i << 8);
        bf16 h, l; split2(p, h, l);
        ph[idx] = h; pl[idx] = l;
    }
}

// ---------------------------------------------------------------------------
extern "C" void kernel_launch(void* const* d_in, const int* in_sizes, int n_in,
                              void* d_out, int out_size)
{
    const float*        input1 = (const float*)d_in[0];          // [B,S1,D]
    const float*        input2 = (const float*)d_in[1];          // [B,S2,D]
    const unsigned int* mask   = (const unsigned int*)d_in[2];   // [B,S1] words
    const float*        weight = (const float*)d_in[3];          // [D,D]
    float*              out    = (float*)d_out;                  // [B,S2,D]

    bf16 *in1h,*in1l,*in2h,*in2l,*wh,*wl,*o1h,*o1l,*t1h,*t1l,*ph,*pl;
    float *scoresp;
    cudaGetSymbolAddress((void**)&in1h, g_in1h);
    cudaGetSymbolAddress((void**)&in1l, g_in1l);
    cudaGetSymbolAddress((void**)&in2h, g_in2h);
    cudaGetSymbolAddress((void**)&in2l, g_in2l);
    cudaGetSymbolAddress((void**)&wh,  g_wh);
    cudaGetSymbolAddress((void**)&wl,  g_wl);
    cudaGetSymbolAddress((void**)&o1h, g_o1h);
    cudaGetSymbolAddress((void**)&o1l, g_o1l);
    cudaGetSymbolAddress((void**)&t1h, g_t1h);
    cudaGetSymbolAddress((void**)&t1l, g_t1l);
    cudaGetSymbolAddress((void**)&ph,  g_ph);
    cudaGetSymbolAddress((void**)&pl,  g_pl);
    cudaGetSymbolAddress((void**)&scoresp, g_scores);

    const int SMEM_BYTES = 73728;   // 3 stages x 4 arrays x 6144B
    cudaFuncSetAttribute(gemm_mma<0>, cudaFuncAttributeMaxDynamicSharedMemorySize, SMEM_BYTES);
    cudaFuncSetAttribute(gemm_mma<1>, cudaFuncAttributeMaxDynamicSharedMemorySize, SMEM_BYTES);
    cudaFuncSetAttribute(gemm_mma<2>, cudaFuncAttributeMaxDynamicSharedMemorySize, SMEM_BYTES);

    const size_t n1 = (size_t)BATCH * SEQ1 * DIM;

    // 0) splits + transpose-split of input1
    split_kernel<<<(unsigned)(n1 / 1024), 256>>>(input1, in1h, in1l);
    split_kernel<<<(unsigned)(n1 / 1024), 256>>>(input2, in2h, in2l);
    split_kernel<<<(unsigned)((size_t)DIM * DIM / 1024), 256>>>(weight, wh, wl);
    transpose_split<<<dim3(SEQ1 / 32, DIM / 32, BATCH), 256>>>(input1, t1h, t1l);

    // 1) out1 = input1 @ weight^T  (NT, split bf16 out)
    gemm_mma<2><<<dim3(DIM / 128, (BATCH * SEQ1) / 128, 1), 256, SMEM_BYTES>>>(
        in1h, in1l, wh, wl, nullptr, o1h, o1l, nullptr,
        BATCH * SEQ1, DIM, DIM, 0, 0, 0, 0);

    // 2) scoresT[b,t,s] = input2[b,t,:] . out1[b,s,:]  (batched NT, mask on s)
    gemm_mma<1><<<dim3(SEQ1 / 128, SEQ2 / 128, BATCH), 256, SMEM_BYTES>>>(
        in2h, in2l, o1h, o1l, scoresp, nullptr, nullptr, mask,
        SEQ2, SEQ1, DIM,
        (size_t)SEQ2 * DIM, (size_t)SEQ1 * DIM, (size_t)SEQ2 * SEQ1, (size_t)SEQ1);

    // 3) softmax over s + split probabilities
    softmax_rows<<<BATCH * SEQ2, 256>>>(scoresp, ph, pl);

    // 4) out[b,t,d] = sum_s P[b,t,s] * input1[b,s,d]  (NT vs input1^T, fp32 out)
    gemm_mma<0><<<dim3(DIM / 128, SEQ2 / 128, BATCH), 256, SMEM_BYTES>>>(
        ph, pl, t1h, t1l, out, nullptr, nullptr, nullptr,
        SEQ2, DIM, SEQ1,
        (size_t)SEQ2 * SEQ1, (size_t)DIM * SEQ1, (size_t)SEQ2 * DIM, 0);
}

// round 8
// speedup vs baseline: 2.2742x; 1.7293x over previous
#include <cuda_runtime.h>
#include <cuda_bf16.h>
#include <stdint.h>

#define BATCH 8
#define SEQ1  2048
#define SEQ2  2048
#define DIM   1024

using bf16 = __nv_bfloat16;

// ---------------- scratch (static __device__, zero-init, no allocation) -----
__device__ int   g_idx[BATCH * SEQ1];              // compacted s indices
__device__ int   g_nb[BATCH];                      // # unmasked rows per batch
__device__ bf16  g_in1h[(size_t)BATCH*SEQ1*DIM];   // compacted input1 split
__device__ bf16  g_in1l[(size_t)BATCH*SEQ1*DIM];
__device__ bf16  g_in2h[(size_t)BATCH*SEQ2*DIM];
__device__ bf16  g_in2l[(size_t)BATCH*SEQ2*DIM];
__device__ bf16  g_wh[(size_t)DIM*DIM];
__device__ bf16  g_wl[(size_t)DIM*DIM];
__device__ bf16  g_o1h[(size_t)BATCH*SEQ1*DIM];    // compacted out1 split
__device__ bf16  g_o1l[(size_t)BATCH*SEQ1*DIM];
__device__ bf16  g_t1h[(size_t)BATCH*DIM*SEQ1];    // compacted input1^T split
__device__ bf16  g_t1l[(size_t)BATCH*DIM*SEQ1];
__device__ float g_scores[(size_t)BATCH*SEQ2*SEQ1];
__device__ bf16  g_ph[(size_t)BATCH*SEQ2*SEQ1];
__device__ bf16  g_pl[(size_t)BATCH*SEQ2*SEQ1];

__device__ __forceinline__ void split2(float x, bf16 &h, bf16 &l) {
    h = __float2bfloat16(x);
    l = __float2bfloat16(x - __bfloat162float(h));
}

// ---------------- mask compaction: per-batch ascending index list -----------
__global__ __launch_bounds__(256)
void build_idx(const unsigned* __restrict__ mask, int* __restrict__ idx,
               int* __restrict__ nb)
{
    const int b = blockIdx.x, tid = threadIdx.x;
    const int lane = tid & 31, wid = tid >> 5;
    const unsigned* mk = mask + (size_t)b * SEQ1;
    __shared__ int wsum[8];

    int bits[8], c = 0;
#pragma unroll
    for (int k = 0; k < 8; k++) {
        bits[k] = (mk[tid * 8 + k] != 0u) ? 1 : 0;
        c += bits[k];
    }
    int pre = c;                       // inclusive scan within warp
#pragma unroll
    for (int o = 1; o < 32; o <<= 1) {
        int n = __shfl_up_sync(0xffffffffu, pre, o);
        if (lane >= o) pre += n;
    }
    if (lane == 31) wsum[wid] = pre;
    __syncthreads();
    int woff = 0;
    for (int w = 0; w < wid; w++) woff += wsum[w];
    int pos = woff + pre - c;          // exclusive prefix
#pragma unroll
    for (int k = 0; k < 8; k++)
        if (bits[k]) idx[b * SEQ1 + pos++] = tid * 8 + k;
    if (tid == 255) nb[b] = woff + pre;
}

// ---------------- split (fp32 -> hi/lo bf16), plain -------------------------
__global__ __launch_bounds__(256) void split_kernel(const float* __restrict__ x,
                                                    bf16* __restrict__ h,
                                                    bf16* __restrict__ l) {
    size_t i = ((size_t)blockIdx.x * 256 + threadIdx.x) * 4;
    float4 v = *(const float4*)(x + i);
    bf16 h0,h1,h2,h3,l0,l1,l2,l3;
    split2(v.x,h0,l0); split2(v.y,h1,l1); split2(v.z,h2,l2); split2(v.w,h3,l3);
    __nv_bfloat162 a, b;
    a.x=h0; a.y=h1; b.x=h2; b.y=h3;
    ((__nv_bfloat162*)(h+i))[0] = a; ((__nv_bfloat162*)(h+i))[1] = b;
    a.x=l0; a.y=l1; b.x=l2; b.y=l3;
    ((__nv_bfloat162*)(l+i))[0] = a; ((__nv_bfloat162*)(l+i))[1] = b;
}

// ---------------- gather + split + transpose of input1 (compacted) ----------
// in1c[b,j,d] = split(input1[b, idx[j], d]),  t1c[b,d,j] = same transposed.
// Rows j >= nb (up to pad128) are written as zeros.
__global__ __launch_bounds__(256)
void gather_split(const float* __restrict__ x, const int* __restrict__ idxp,
                  const int* __restrict__ nbp,
                  bf16* __restrict__ ch, bf16* __restrict__ cl,
                  bf16* __restrict__ th, bf16* __restrict__ tl)
{
    const int b  = blockIdx.z;
    const int j0 = blockIdx.x * 32, d0 = blockIdx.y * 32;
    const int nb = nbp[b];
    const int npad = (nb + 127) & ~127;
    if (j0 >= npad) return;

    const int tx = threadIdx.x & 31, ty = threadIdx.x >> 5;
    __shared__ float t[32][33];
    __shared__ int rows[32];
    if (threadIdx.x < 32)
        rows[threadIdx.x] =
            (j0 + threadIdx.x < nb) ? idxp[b * SEQ1 + j0 + threadIdx.x] : -1;
    __syncthreads();
#pragma unroll
    for (int k = 0; k < 4; k++) {
        const int j = ty + 8 * k;
        const int s = rows[j];
        t[j][tx] = (s >= 0) ? x[((size_t)b * SEQ1 + s) * DIM + d0 + tx] : 0.0f;
    }
    __syncthreads();
#pragma unroll
    for (int k = 0; k < 4; k++) {        // normal orientation
        const int j = ty + 8 * k;
        bf16 h, l; split2(t[j][tx], h, l);
        const size_t o = ((size_t)b * SEQ1 + j0 + j) * DIM + d0 + tx;
        ch[o] = h; cl[o] = l;
    }
#pragma unroll
    for (int k = 0; k < 4; k++) {        // transposed orientation
        bf16 h, l; split2(t[tx][ty + 8 * k], h, l);
        const size_t o = ((size_t)b * DIM + d0 + ty + 8 * k) * SEQ1 + j0 + tx;
        th[o] = h; tl[o] = l;
    }
}

// ---------------- PTX helpers ----------------
#define CP16(dst, src) asm volatile("cp.async.cg.shared.global [%0], [%1], 16;\n" :: "r"(dst), "l"(src))
#define CP_COMMIT()    asm volatile("cp.async.commit_group;\n")
#define CP_WAIT1()     asm volatile("cp.async.wait_group 1;\n")
#define CP_WAIT0()     asm volatile("cp.async.wait_group 0;\n")

#define MMA_BF16(d, a, b) asm volatile( \
  "mma.sync.aligned.m16n8k16.row.col.f32.bf16.bf16.f32 " \
  "{%0,%1,%2,%3},{%4,%5,%6,%7},{%8,%9},{%0,%1,%2,%3};\n" \
  : "+f"(d[0]), "+f"(d[1]), "+f"(d[2]), "+f"(d[3]) \
  : "r"(a[0]), "r"(a[1]), "r"(a[2]), "r"(a[3]), "r"(b[0]), "r"(b[1]))

#define LDSM_X4(r0, r1, r2, r3, addr) asm volatile( \
  "ldmatrix.sync.aligned.m8n8.x4.shared.b16 {%0,%1,%2,%3}, [%4];\n" \
  : "=r"(r0), "=r"(r1), "=r"(r2), "=r"(r3) : "r"(addr))

// ---------------------------------------------------------------------------
// Split-bf16 HMMA NT GEMM (round-7 proven core): C = A*B^T, 3-product split,
// 128x128 tile, BK=16, 8 warps, 3-stage cp.async, ldmatrix.x4 fragments,
// product-major MMA ordering (same-acc distance 16).
//   EPI=0: fp32 out.  EPI=2: split-bf16 out.
//   BND=0: none.  BND=1: skip tiles with m0 >= pad128(nb[bz]).
//   BND=2: skip tiles with n0 >= pad128(nb[bz]).  BND=3: K = pad16(nb[bz]).
//   Ks = row stride of A and B (may exceed logical K).
// ---------------------------------------------------------------------------
template<int EPI, int BND>
__global__ __launch_bounds__(256, 2)
void gemm_mma(const bf16* __restrict__ Ahg, const bf16* __restrict__ Alg,
              const bf16* __restrict__ Bhg, const bf16* __restrict__ Blg,
              float* __restrict__ Cfg, bf16* __restrict__ Chg, bf16* __restrict__ Clg,
              const int* __restrict__ nbp,
              int N, int K, int Ks,
              size_t sA, size_t sB, size_t sC)
{
    extern __shared__ __align__(16) char dsm[];
    const uint32_t smem0 = (uint32_t)__cvta_generic_to_shared(dsm);
    constexpr uint32_t ARR = 6144u;      // 128 rows x 24 halves x 2B
    constexpr uint32_t STAGE = 4u * ARR; // 24576B; 3 stages = 73728B

    const int tid  = threadIdx.x;
    const int warp = tid >> 5, lane = tid & 31;
    const int wm = warp >> 2, wn = warp & 3;
    const int g  = lane >> 2, tq = lane & 3;
    const int bz = blockIdx.z;
    const int m0 = blockIdx.y * 128, n0 = blockIdx.x * 128;

    int Klogic = K;
    if (BND) {
        const int nb = nbp[bz];
        const int npad = (nb + 127) & ~127;
        if (BND == 1 && m0 >= npad) return;
        if (BND == 2 && n0 >= npad) return;
        if (BND == 3) Klogic = (nb + 15) & ~15;
    }

    const bf16* Ah = Ahg + (size_t)bz * sA + (size_t)m0 * Ks;
    const bf16* Al = Alg + (size_t)bz * sA + (size_t)m0 * Ks;
    const bf16* Bh = Bhg + (size_t)bz * sB + (size_t)n0 * Ks;
    const bf16* Bl = Blg + (size_t)bz * sB + (size_t)n0 * Ks;

    const int r_ = tid >> 1, u_ = tid & 1;
    const uint32_t offc = (uint32_t)(r_ * 48 + u_ * 16);

    const uint32_t aOff =
        (uint32_t)(((lane & 15) * 24 + ((lane >> 4) & 1) * 8) * 2);
    const uint32_t bOffL =
        (uint32_t)((((lane & 7) + ((lane >> 4) & 1) * 8) * 24 +
                    ((lane >> 3) & 1) * 8) * 2);

    float acc[4][4][4];
#pragma unroll
    for (int mt = 0; mt < 4; mt++)
#pragma unroll
        for (int nt = 0; nt < 4; nt++)
#pragma unroll
            for (int c = 0; c < 4; c++) acc[mt][nt][c] = 0.0f;

    const int NC = Klogic >> 4;

#define ISSUE(stg, kk) do {                                                  \
        uint32_t sb_ = smem0 + (uint32_t)(stg) * STAGE;                      \
        size_t go_ = (size_t)r_ * Ks + (kk) + u_ * 8;                        \
        CP16(sb_ +           offc, Ah + go_);                                \
        CP16(sb_ +    ARR +  offc, Al + go_);                                \
        CP16(sb_ + 2u*ARR +  offc, Bh + go_);                                \
        CP16(sb_ + 3u*ARR +  offc, Bl + go_);                                \
        CP_COMMIT();                                                         \
    } while (0)

    ISSUE(0, 0);
    if (NC > 1) ISSUE(1, 16);

    for (int i = 0; i < NC; i++) {
        if (i + 1 < NC) { CP_WAIT1(); } else { CP_WAIT0(); }
        __syncthreads();
        if (i + 2 < NC) ISSUE((i + 2) % 3, (i + 2) << 4);

        const uint32_t stb = smem0 + (uint32_t)(i % 3) * STAGE;

        uint32_t bh4[2][4], bl4[2][4];
#pragma unroll
        for (int p = 0; p < 2; p++) {
            const uint32_t bo =
                stb + 2u * ARR + (uint32_t)((wn * 32 + p * 16) * 48) + bOffL;
            LDSM_X4(bh4[p][0], bh4[p][1], bh4[p][2], bh4[p][3], bo);
            LDSM_X4(bl4[p][0], bl4[p][1], bl4[p][2], bl4[p][3], bo + ARR);
        }
        uint32_t ah[4][4];
#pragma unroll
        for (int mt = 0; mt < 4; mt++) {
            const uint32_t ao =
                stb + (uint32_t)((wm * 64 + mt * 16) * 48) + aOff;
            LDSM_X4(ah[mt][0], ah[mt][1], ah[mt][2], ah[mt][3], ao);
        }
#pragma unroll
        for (int mt = 0; mt < 4; mt++)
#pragma unroll
            for (int nt = 0; nt < 4; nt++)
                MMA_BF16(acc[mt][nt], ah[mt], (&bh4[nt >> 1][(nt & 1) * 2]));
#pragma unroll
        for (int mt = 0; mt < 4; mt++)
#pragma unroll
            for (int nt = 0; nt < 4; nt++)
                MMA_BF16(acc[mt][nt], ah[mt], (&bl4[nt >> 1][(nt & 1) * 2]));
#pragma unroll
        for (int mt = 0; mt < 4; mt++) {
            const uint32_t ao =
                stb + ARR + (uint32_t)((wm * 64 + mt * 16) * 48) + aOff;
            uint32_t al[4];
            LDSM_X4(al[0], al[1], al[2], al[3], ao);
#pragma unroll
            for (int nt = 0; nt < 4; nt++)
                MMA_BF16(acc[mt][nt], al, (&bh4[nt >> 1][(nt & 1) * 2]));
        }
    }
#undef ISSUE

    // ---------------- epilogue ----------------
    float* Cf = (EPI == 0) ? Cfg + (size_t)bz * sC : nullptr;
    bf16*  Ch = (EPI == 2) ? Chg + (size_t)bz * sC : nullptr;
    bf16*  Cl = (EPI == 2) ? Clg + (size_t)bz * sC : nullptr;

#pragma unroll
    for (int mt = 0; mt < 4; mt++) {
        const int r0 = m0 + wm * 64 + mt * 16 + g;
#pragma unroll
        for (int nt = 0; nt < 4; nt++) {
            const int col = n0 + wn * 32 + nt * 8 + tq * 2;
            const float c0 = acc[mt][nt][0], c1 = acc[mt][nt][1];
            const float c2 = acc[mt][nt][2], c3 = acc[mt][nt][3];
            if (EPI == 0) {
                *(float2*)(Cf + (size_t)r0 * N + col)       = make_float2(c0, c1);
                *(float2*)(Cf + (size_t)(r0 + 8) * N + col) = make_float2(c2, c3);
            } else {
                bf16 h0,h1,h2,h3,l0,l1,l2,l3;
                split2(c0,h0,l0); split2(c1,h1,l1); split2(c2,h2,l2); split2(c3,h3,l3);
                __nv_bfloat162 t;
                t.x=h0; t.y=h1; *(__nv_bfloat162*)(Ch + (size_t)r0*N + col)     = t;
                t.x=h2; t.y=h3; *(__nv_bfloat162*)(Ch + (size_t)(r0+8)*N + col) = t;
                t.x=l0; t.y=l1; *(__nv_bfloat162*)(Cl + (size_t)r0*N + col)     = t;
                t.x=l2; t.y=l3; *(__nv_bfloat162*)(Cl + (size_t)(r0+8)*N + col) = t;
            }
        }
    }
}

// ---------------------------------------------------------------------------
// Variable-length row softmax over compacted scores [b,t,j], j in [0, nb).
// Writes split probabilities; zero-fills padding up to pad128(nb).
// ---------------------------------------------------------------------------
__global__ __launch_bounds__(256)
void softmax_rows(const float* __restrict__ scores, const int* __restrict__ nbp,
                  bf16* __restrict__ ph, bf16* __restrict__ pl)
{
    const int tid = threadIdx.x;
    const int b = blockIdx.x >> 11;         // SEQ2 = 2048 rows per batch
    const int nb = nbp[b];
    const int npad = (nb + 127) & ~127;
    const size_t base = (size_t)blockIdx.x * SEQ1;
    const float* row = scores + base;

    float v[8];
    float mx = -3.4e38f;
#pragma unroll
    for (int i = 0; i < 8; i++) {
        const int j = tid + (i << 8);
        v[i] = (j < nb) ? row[j] : -3.4e38f;
        mx = fmaxf(mx, v[i]);
    }
#pragma unroll
    for (int o = 16; o > 0; o >>= 1)
        mx = fmaxf(mx, __shfl_xor_sync(0xffffffffu, mx, o));

    __shared__ float smax[8];
    __shared__ float ssum[8];
    if ((tid & 31) == 0) smax[tid >> 5] = mx;
    __syncthreads();
    mx = smax[0];
#pragma unroll
    for (int w = 1; w < 8; w++) mx = fmaxf(mx, smax[w]);

    float s = 0.0f;
#pragma unroll
    for (int i = 0; i < 8; i++) {
        const int j = tid + (i << 8);
        v[i] = (j < nb) ? __expf(v[i] - mx) : 0.0f;
        s += v[i];
    }
#pragma unroll
    for (int o = 16; o > 0; o >>= 1)
        s += __shfl_xor_sync(0xffffffffu, s, o);
    if ((tid & 31) == 0) ssum[tid >> 5] = s;
    __syncthreads();
    s = ssum[0];
#pragma unroll
    for (int w = 1; w < 8; w++) s += ssum[w];

    const float inv = 1.0f / s;
#pragma unroll
    for (int i = 0; i < 8; i++) {
        const int j = tid + (i << 8);
        if (j < npad) {
            bf16 h, l;
            if (j < nb) split2(v[i] * inv, h, l);
            else { h = __float2bfloat16(0.0f); l = h; }
            ph[base + j] = h; pl[base + j] = l;
        }
    }
}

// ---------------------------------------------------------------------------
extern "C" void kernel_launch(void* const* d_in, const int* in_sizes, int n_in,
                              void* d_out, int out_size)
{
    const float*        input1 = (const float*)d_in[0];          // [B,S1,D]
    const float*        input2 = (const float*)d_in[1];          // [B,S2,D]
    const unsigned int* mask   = (const unsigned int*)d_in[2];   // [B,S1] words
    const float*        weight = (const float*)d_in[3];          // [D,D]
    float*              out    = (float*)d_out;                  // [B,S2,D]

    bf16 *in1h,*in1l,*in2h,*in2l,*wh,*wl,*o1h,*o1l,*t1h,*t1l,*ph,*pl;
    float *scoresp; int *idxp, *nbp;
    cudaGetSymbolAddress((void**)&idxp, g_idx);
    cudaGetSymbolAddress((void**)&nbp,  g_nb);
    cudaGetSymbolAddress((void**)&in1h, g_in1h);
    cudaGetSymbolAddress((void**)&in1l, g_in1l);
    cudaGetSymbolAddress((void**)&in2h, g_in2h);
    cudaGetSymbolAddress((void**)&in2l, g_in2l);
    cudaGetSymbolAddress((void**)&wh,  g_wh);
    cudaGetSymbolAddress((void**)&wl,  g_wl);
    cudaGetSymbolAddress((void**)&o1h, g_o1h);
    cudaGetSymbolAddress((void**)&o1l, g_o1l);
    cudaGetSymbolAddress((void**)&t1h, g_t1h);
    cudaGetSymbolAddress((void**)&t1l, g_t1l);
    cudaGetSymbolAddress((void**)&ph,  g_ph);
    cudaGetSymbolAddress((void**)&pl,  g_pl);
    cudaGetSymbolAddress((void**)&scoresp, g_scores);

    const int SMEM_BYTES = 73728;
    cudaFuncSetAttribute(gemm_mma<2,1>, cudaFuncAttributeMaxDynamicSharedMemorySize, SMEM_BYTES);
    cudaFuncSetAttribute(gemm_mma<0,2>, cudaFuncAttributeMaxDynamicSharedMemorySize, SMEM_BYTES);
    cudaFuncSetAttribute(gemm_mma<0,3>, cudaFuncAttributeMaxDynamicSharedMemorySize, SMEM_BYTES);

    const size_t n1 = (size_t)BATCH * SEQ1 * DIM;

    // 0) mask compaction + operand prep
    build_idx<<<BATCH, 256>>>(mask, idxp, nbp);
    split_kernel<<<(unsigned)(n1 / 1024), 256>>>(input2, in2h, in2l);
    split_kernel<<<(unsigned)((size_t)DIM * DIM / 1024), 256>>>(weight, wh, wl);
    gather_split<<<dim3(SEQ1 / 32, DIM / 32, BATCH), 256>>>(
        input1, idxp, nbp, in1h, in1l, t1h, t1l);

    // 1) out1c[b,j,:] = in1c[b,j,:] @ W^T  (compacted M, split-bf16 out)
    gemm_mma<2,1><<<dim3(DIM / 128, SEQ1 / 128, BATCH), 256, SMEM_BYTES>>>(
        in1h, in1l, wh, wl, nullptr, o1h, o1l, nbp,
        DIM, DIM, DIM,
        (size_t)SEQ1 * DIM, 0, (size_t)SEQ1 * DIM);

    // 2) scoresT[b,t,j] = in2[b,t,:] . out1c[b,j,:]  (compacted N, no mask!)
    gemm_mma<0,2><<<dim3(SEQ1 / 128, SEQ2 / 128, BATCH), 256, SMEM_BYTES>>>(
        in2h, in2l, o1h, o1l, scoresp, nullptr, nullptr, nbp,
        SEQ1, DIM, DIM,
        (size_t)SEQ2 * DIM, (size_t)SEQ1 * DIM, (size_t)SEQ2 * SEQ1);

    // 3) softmax over compacted j + split probabilities (zero-padded)
    softmax_rows<<<BATCH * SEQ2, 256>>>(scoresp, nbp, ph, pl);

    // 4) out[b,t,d] = sum_j P[b,t,j] * in1c[b,j,d]  (compacted K, NT vs t1c)
    gemm_mma<0,3><<<dim3(DIM / 128, SEQ2 / 128, BATCH), 256, SMEM_BYTES>>>(
        ph, pl, t1h, t1l, out, nullptr, nullptr, nbp,
        DIM, SEQ1, SEQ1,
        (size_t)SEQ2 * SEQ1, (size_t)DIM * SEQ1, (size_t)SEQ2 * DIM);
}

// round 9
// speedup vs baseline: 2.8517x; 1.2539x over previous
#include <cuda_runtime.h>
#include <cuda_bf16.h>
#include <cuda_fp16.h>
#include <stdint.h>

#define BATCH 8
#define SEQ1  2048
#define SEQ2  2048
#define DIM   1024

using bf16 = __nv_bfloat16;

// ---------------- scratch (static __device__, zero-init, no allocation) -----
__device__ int    g_idx[BATCH * SEQ1];              // compacted s indices
__device__ int    g_nb[BATCH];                      // # unmasked rows per batch
__device__ bf16   g_in1h[(size_t)BATCH*SEQ1*DIM];   // compacted input1 split
__device__ bf16   g_in1l[(size_t)BATCH*SEQ1*DIM];
__device__ bf16   g_in2h[(size_t)BATCH*SEQ2*DIM];
__device__ bf16   g_in2l[(size_t)BATCH*SEQ2*DIM];
__device__ bf16   g_wh[(size_t)DIM*DIM];
__device__ bf16   g_wl[(size_t)DIM*DIM];
__device__ bf16   g_o1h[(size_t)BATCH*SEQ1*DIM];    // compacted out1 split
__device__ bf16   g_o1l[(size_t)BATCH*SEQ1*DIM];
__device__ __half g_t1f[(size_t)BATCH*DIM*SEQ1];    // compacted input1^T fp16
__device__ float  g_scores[(size_t)BATCH*SEQ2*SEQ1];
__device__ __half g_pf[(size_t)BATCH*SEQ2*SEQ1];    // probabilities fp16

__device__ __forceinline__ void split2(float x, bf16 &h, bf16 &l) {
    h = __float2bfloat16(x);
    l = __float2bfloat16(x - __bfloat162float(h));
}

// ---------------- mask compaction: per-batch ascending index list -----------
__global__ __launch_bounds__(256)
void build_idx(const unsigned* __restrict__ mask, int* __restrict__ idx,
               int* __restrict__ nb)
{
    const int b = blockIdx.x, tid = threadIdx.x;
    const int lane = tid & 31, wid = tid >> 5;
    const unsigned* mk = mask + (size_t)b * SEQ1;
    __shared__ int wsum[8];

    int bits[8], c = 0;
#pragma unroll
    for (int k = 0; k < 8; k++) {
        bits[k] = (mk[tid * 8 + k] != 0u) ? 1 : 0;
        c += bits[k];
    }
    int pre = c;
#pragma unroll
    for (int o = 1; o < 32; o <<= 1) {
        int n = __shfl_up_sync(0xffffffffu, pre, o);
        if (lane >= o) pre += n;
    }
    if (lane == 31) wsum[wid] = pre;
    __syncthreads();
    int woff = 0;
    for (int w = 0; w < wid; w++) woff += wsum[w];
    int pos = woff + pre - c;
#pragma unroll
    for (int k = 0; k < 8; k++)
        if (bits[k]) idx[b * SEQ1 + pos++] = tid * 8 + k;
    if (tid == 255) nb[b] = woff + pre;
}

// ---------------- split (fp32 -> hi/lo bf16), plain -------------------------
__global__ __launch_bounds__(256) void split_kernel(const float* __restrict__ x,
                                                    bf16* __restrict__ h,
                                                    bf16* __restrict__ l) {
    size_t i = ((size_t)blockIdx.x * 256 + threadIdx.x) * 4;
    float4 v = *(const float4*)(x + i);
    bf16 h0,h1,h2,h3,l0,l1,l2,l3;
    split2(v.x,h0,l0); split2(v.y,h1,l1); split2(v.z,h2,l2); split2(v.w,h3,l3);
    __nv_bfloat162 a, b;
    a.x=h0; a.y=h1; b.x=h2; b.y=h3;
    ((__nv_bfloat162*)(h+i))[0] = a; ((__nv_bfloat162*)(h+i))[1] = b;
    a.x=l0; a.y=l1; b.x=l2; b.y=l3;
    ((__nv_bfloat162*)(l+i))[0] = a; ((__nv_bfloat162*)(l+i))[1] = b;
}

// ---------------- gather + split + transpose of input1 (compacted) ----------
// in1c[b,j,d] = split_bf16(input1[b, idx[j], d])  (for GEMM1)
// t1f[b,d,j]  = fp16(input1[b, idx[j], d])        (for GEMM3, single fp16)
// Rows j >= nb (up to pad128) are zeros.
__global__ __launch_bounds__(256)
void gather_split(const float* __restrict__ x, const int* __restrict__ idxp,
                  const int* __restrict__ nbp,
                  bf16* __restrict__ ch, bf16* __restrict__ cl,
                  __half* __restrict__ tf)
{
    const int b  = blockIdx.z;
    const int j0 = blockIdx.x * 32, d0 = blockIdx.y * 32;
    const int nb = nbp[b];
    const int npad = (nb + 127) & ~127;
    if (j0 >= npad) return;

    const int tx = threadIdx.x & 31, ty = threadIdx.x >> 5;
    __shared__ float t[32][33];
    __shared__ int rows[32];
    if (threadIdx.x < 32)
        rows[threadIdx.x] =
            (j0 + threadIdx.x < nb) ? idxp[b * SEQ1 + j0 + threadIdx.x] : -1;
    __syncthreads();
#pragma unroll
    for (int k = 0; k < 4; k++) {
        const int j = ty + 8 * k;
        const int s = rows[j];
        t[j][tx] = (s >= 0) ? x[((size_t)b * SEQ1 + s) * DIM + d0 + tx] : 0.0f;
    }
    __syncthreads();
#pragma unroll
    for (int k = 0; k < 4; k++) {        // normal orientation, bf16 split
        const int j = ty + 8 * k;
        bf16 h, l; split2(t[j][tx], h, l);
        const size_t o = ((size_t)b * SEQ1 + j0 + j) * DIM + d0 + tx;
        ch[o] = h; cl[o] = l;
    }
#pragma unroll
    for (int k = 0; k < 4; k++) {        // transposed orientation, fp16
        const size_t o = ((size_t)b * DIM + d0 + ty + 8 * k) * SEQ1 + j0 + tx;
        tf[o] = __float2half(t[tx][ty + 8 * k]);
    }
}

// ---------------- PTX helpers ----------------
#define CP16(dst, src) asm volatile("cp.async.cg.shared.global [%0], [%1], 16;\n" :: "r"(dst), "l"(src))
#define CP_COMMIT()    asm volatile("cp.async.commit_group;\n")
#define CP_WAIT1()     asm volatile("cp.async.wait_group 1;\n")
#define CP_WAIT0()     asm volatile("cp.async.wait_group 0;\n")

#define MMA_BF16(d, a, b) asm volatile( \
  "mma.sync.aligned.m16n8k16.row.col.f32.bf16.bf16.f32 " \
  "{%0,%1,%2,%3},{%4,%5,%6,%7},{%8,%9},{%0,%1,%2,%3};\n" \
  : "+f"(d[0]), "+f"(d[1]), "+f"(d[2]), "+f"(d[3]) \
  : "r"(a[0]), "r"(a[1]), "r"(a[2]), "r"(a[3]), "r"(b[0]), "r"(b[1]))

#define MMA_F16(d, a, b) asm volatile( \
  "mma.sync.aligned.m16n8k16.row.col.f32.f16.f16.f32 " \
  "{%0,%1,%2,%3},{%4,%5,%6,%7},{%8,%9},{%0,%1,%2,%3};\n" \
  : "+f"(d[0]), "+f"(d[1]), "+f"(d[2]), "+f"(d[3]) \
  : "r"(a[0]), "r"(a[1]), "r"(a[2]), "r"(a[3]), "r"(b[0]), "r"(b[1]))

#define LDSM_X4(r0, r1, r2, r3, addr) asm volatile( \
  "ldmatrix.sync.aligned.m8n8.x4.shared.b16 {%0,%1,%2,%3}, [%4];\n" \
  : "=r"(r0), "=r"(r1), "=r"(r2), "=r"(r3) : "r"(addr))

// ---------------------------------------------------------------------------
// HMMA NT GEMM (round-8 proven core): C = A*B^T. 128x128 tile, BK=16,
// 8 warps (64x32 each), 3-stage cp.async, ldmatrix.x4, product-major order.
//   PROD=3: split-bf16 3-product (Ah*Bh + Ah*Bl + Al*Bh), 4 operand arrays.
//   PROD=1: single-product fp16, 2 operand arrays.
//   EPI=0: fp32 out.  EPI=2: split-bf16 out.
//   BND=1: skip m0 >= pad128(nb).  BND=2: skip n0 >= pad128(nb).
//   BND=3: K = pad16(nb).   Ks = row stride of A/B.
// ---------------------------------------------------------------------------
template<int EPI, int BND, int PROD>
__global__ __launch_bounds__(256, 2)
void gemm_mma(const bf16* __restrict__ Ahg, const bf16* __restrict__ Alg,
              const bf16* __restrict__ Bhg, const bf16* __restrict__ Blg,
              float* __restrict__ Cfg, bf16* __restrict__ Chg, bf16* __restrict__ Clg,
              const int* __restrict__ nbp,
              int N, int K, int Ks,
              size_t sA, size_t sB, size_t sC)
{
    extern __shared__ __align__(16) char dsm[];
    const uint32_t smem0 = (uint32_t)__cvta_generic_to_shared(dsm);
    constexpr uint32_t ARR = 6144u;                       // 128 x 24 halves x 2B
    constexpr uint32_t NARR = (PROD == 3) ? 4u : 2u;
    constexpr uint32_t STAGE = NARR * ARR;
    constexpr uint32_t BOFF = (PROD == 3) ? 2u * ARR : ARR;  // B base in stage

    const int tid  = threadIdx.x;
    const int warp = tid >> 5, lane = tid & 31;
    const int wm = warp >> 2, wn = warp & 3;
    const int g  = lane >> 2, tq = lane & 3;
    const int bz = blockIdx.z;
    const int m0 = blockIdx.y * 128, n0 = blockIdx.x * 128;

    int Klogic = K;
    if (BND) {
        const int nb = nbp[bz];
        const int npad = (nb + 127) & ~127;
        if (BND == 1 && m0 >= npad) return;
        if (BND == 2 && n0 >= npad) return;
        if (BND == 3) Klogic = (nb + 15) & ~15;
    }

    const bf16* Ah = Ahg + (size_t)bz * sA + (size_t)m0 * Ks;
    const bf16* Al = (PROD == 3) ? Alg + (size_t)bz * sA + (size_t)m0 * Ks : nullptr;
    const bf16* Bh = Bhg + (size_t)bz * sB + (size_t)n0 * Ks;
    const bf16* Bl = (PROD == 3) ? Blg + (size_t)bz * sB + (size_t)n0 * Ks : nullptr;

    const int r_ = tid >> 1, u_ = tid & 1;
    const uint32_t offc = (uint32_t)(r_ * 48 + u_ * 16);

    const uint32_t aOff =
        (uint32_t)(((lane & 15) * 24 + ((lane >> 4) & 1) * 8) * 2);
    const uint32_t bOffL =
        (uint32_t)((((lane & 7) + ((lane >> 4) & 1) * 8) * 24 +
                    ((lane >> 3) & 1) * 8) * 2);

    float acc[4][4][4];
#pragma unroll
    for (int mt = 0; mt < 4; mt++)
#pragma unroll
        for (int nt = 0; nt < 4; nt++)
#pragma unroll
            for (int c = 0; c < 4; c++) acc[mt][nt][c] = 0.0f;

    const int NC = Klogic >> 4;

    auto issue = [&](int stg, int kk) {
        const uint32_t sb_ = smem0 + (uint32_t)stg * STAGE;
        const size_t go_ = (size_t)r_ * Ks + kk + u_ * 8;
        CP16(sb_ + offc, Ah + go_);
        if (PROD == 3) CP16(sb_ + ARR + offc, Al + go_);
        CP16(sb_ + BOFF + offc, Bh + go_);
        if (PROD == 3) CP16(sb_ + 3u * ARR + offc, Bl + go_);
        CP_COMMIT();
    };

    issue(0, 0);
    if (NC > 1) issue(1, 16);

    for (int i = 0; i < NC; i++) {
        if (i + 1 < NC) { CP_WAIT1(); } else { CP_WAIT0(); }
        __syncthreads();
        if (i + 2 < NC) issue((i + 2) % 3, (i + 2) << 4);

        const uint32_t stb = smem0 + (uint32_t)(i % 3) * STAGE;

        uint32_t bh4[2][4], bl4[2][4];
#pragma unroll
        for (int p = 0; p < 2; p++) {
            const uint32_t bo =
                stb + BOFF + (uint32_t)((wn * 32 + p * 16) * 48) + bOffL;
            LDSM_X4(bh4[p][0], bh4[p][1], bh4[p][2], bh4[p][3], bo);
            if (PROD == 3)
                LDSM_X4(bl4[p][0], bl4[p][1], bl4[p][2], bl4[p][3], bo + ARR);
        }
        uint32_t ah[4][4];
#pragma unroll
        for (int mt = 0; mt < 4; mt++) {
            const uint32_t ao =
                stb + (uint32_t)((wm * 64 + mt * 16) * 48) + aOff;
            LDSM_X4(ah[mt][0], ah[mt][1], ah[mt][2], ah[mt][3], ao);
        }

        // phase 1: Ah*Bh
#pragma unroll
        for (int mt = 0; mt < 4; mt++)
#pragma unroll
            for (int nt = 0; nt < 4; nt++) {
                if (PROD == 3) {
                    MMA_BF16(acc[mt][nt], ah[mt], (&bh4[nt >> 1][(nt & 1) * 2]));
                } else {
                    MMA_F16(acc[mt][nt], ah[mt], (&bh4[nt >> 1][(nt & 1) * 2]));
                }
            }
        if (PROD == 3) {
            // phase 2: Ah*Bl
#pragma unroll
            for (int mt = 0; mt < 4; mt++)
#pragma unroll
                for (int nt = 0; nt < 4; nt++)
                    MMA_BF16(acc[mt][nt], ah[mt], (&bl4[nt >> 1][(nt & 1) * 2]));
            // phase 3: Al*Bh
#pragma unroll
            for (int mt = 0; mt < 4; mt++) {
                const uint32_t ao =
                    stb + ARR + (uint32_t)((wm * 64 + mt * 16) * 48) + aOff;
                uint32_t al[4];
                LDSM_X4(al[0], al[1], al[2], al[3], ao);
#pragma unroll
                for (int nt = 0; nt < 4; nt++)
                    MMA_BF16(acc[mt][nt], al, (&bh4[nt >> 1][(nt & 1) * 2]));
            }
        }
    }

    // ---------------- epilogue ----------------
    float* Cf = (EPI == 0) ? Cfg + (size_t)bz * sC : nullptr;
    bf16*  Ch = (EPI == 2) ? Chg + (size_t)bz * sC : nullptr;
    bf16*  Cl = (EPI == 2) ? Clg + (size_t)bz * sC : nullptr;

#pragma unroll
    for (int mt = 0; mt < 4; mt++) {
        const int r0 = m0 + wm * 64 + mt * 16 + g;
#pragma unroll
        for (int nt = 0; nt < 4; nt++) {
            const int col = n0 + wn * 32 + nt * 8 + tq * 2;
            const float c0 = acc[mt][nt][0], c1 = acc[mt][nt][1];
            const float c2 = acc[mt][nt][2], c3 = acc[mt][nt][3];
            if (EPI == 0) {
                *(float2*)(Cf + (size_t)r0 * N + col)       = make_float2(c0, c1);
                *(float2*)(Cf + (size_t)(r0 + 8) * N + col) = make_float2(c2, c3);
            } else {
                bf16 h0,h1,h2,h3,l0,l1,l2,l3;
                split2(c0,h0,l0); split2(c1,h1,l1); split2(c2,h2,l2); split2(c3,h3,l3);
                __nv_bfloat162 t;
                t.x=h0; t.y=h1; *(__nv_bfloat162*)(Ch + (size_t)r0*N + col)     = t;
                t.x=h2; t.y=h3; *(__nv_bfloat162*)(Ch + (size_t)(r0+8)*N + col) = t;
                t.x=l0; t.y=l1; *(__nv_bfloat162*)(Cl + (size_t)r0*N + col)     = t;
                t.x=l2; t.y=l3; *(__nv_bfloat162*)(Cl + (size_t)(r0+8)*N + col) = t;
            }
        }
    }
}

// ---------------------------------------------------------------------------
// Variable-length row softmax over compacted scores [b,t,j], j in [0, nb).
// Writes single-fp16 probabilities; zero-fills padding up to pad128(nb).
// ---------------------------------------------------------------------------
__global__ __launch_bounds__(256)
void softmax_rows(const float* __restrict__ scores, const int* __restrict__ nbp,
                  __half* __restrict__ pf)
{
    const int tid = threadIdx.x;
    const int b = blockIdx.x >> 11;         // SEQ2 = 2048 rows per batch
    const int nb = nbp[b];
    const int npad = (nb + 127) & ~127;
    const size_t base = (size_t)blockIdx.x * SEQ1;
    const float* row = scores + base;

    float v[8];
    float mx = -3.4e38f;
#pragma unroll
    for (int i = 0; i < 8; i++) {
        const int j = tid + (i << 8);
        v[i] = (j < nb) ? row[j] : -3.4e38f;
        mx = fmaxf(mx, v[i]);
    }
#pragma unroll
    for (int o = 16; o > 0; o >>= 1)
        mx = fmaxf(mx, __shfl_xor_sync(0xffffffffu, mx, o));

    __shared__ float smax[8];
    __shared__ float ssum[8];
    if ((tid & 31) == 0) smax[tid >> 5] = mx;
    __syncthreads();
    mx = smax[0];
#pragma unroll
    for (int w = 1; w < 8; w++) mx = fmaxf(mx, smax[w]);

    float s = 0.0f;
#pragma unroll
    for (int i = 0; i < 8; i++) {
        const int j = tid + (i << 8);
        v[i] = (j < nb) ? __expf(v[i] - mx) : 0.0f;
        s += v[i];
    }
#pragma unroll
    for (int o = 16; o > 0; o >>= 1)
        s += __shfl_xor_sync(0xffffffffu, s, o);
    if ((tid & 31) == 0) ssum[tid >> 5] = s;
    __syncthreads();
    s = ssum[0];
#pragma unroll
    for (int w = 1; w < 8; w++) s += ssum[w];

    const float inv = 1.0f / s;
#pragma unroll
    for (int i = 0; i < 8; i++) {
        const int j = tid + (i << 8);
        if (j < npad)
            pf[base + j] = __float2half((j < nb) ? v[i] * inv : 0.0f);
    }
}

// ---------------------------------------------------------------------------
extern "C" void kernel_launch(void* const* d_in, const int* in_sizes, int n_in,
                              void* d_out, int out_size)
{
    const float*        input1 = (const float*)d_in[0];          // [B,S1,D]
    const float*        input2 = (const float*)d_in[1];          // [B,S2,D]
    const unsigned int* mask   = (const unsigned int*)d_in[2];   // [B,S1] words
    const float*        weight = (const float*)d_in[3];          // [D,D]
    float*              out    = (float*)d_out;                  // [B,S2,D]

    bf16 *in1h,*in1l,*in2h,*in2l,*wh,*wl,*o1h,*o1l;
    __half *t1f, *pf;
    float *scoresp; int *idxp, *nbp;
    cudaGetSymbolAddress((void**)&idxp, g_idx);
    cudaGetSymbolAddress((void**)&nbp,  g_nb);
    cudaGetSymbolAddress((void**)&in1h, g_in1h);
    cudaGetSymbolAddress((void**)&in1l, g_in1l);
    cudaGetSymbolAddress((void**)&in2h, g_in2h);
    cudaGetSymbolAddress((void**)&in2l, g_in2l);
    cudaGetSymbolAddress((void**)&wh,  g_wh);
    cudaGetSymbolAddress((void**)&wl,  g_wl);
    cudaGetSymbolAddress((void**)&o1h, g_o1h);
    cudaGetSymbolAddress((void**)&o1l, g_o1l);
    cudaGetSymbolAddress((void**)&t1f, g_t1f);
    cudaGetSymbolAddress((void**)&pf,  g_pf);
    cudaGetSymbolAddress((void**)&scoresp, g_scores);

    const int SMEM3 = 73728;   // PROD=3: 3 stages x 4 arrays
    const int SMEM1 = 36864;   // PROD=1: 3 stages x 2 arrays
    cudaFuncSetAttribute(gemm_mma<2,1,3>, cudaFuncAttributeMaxDynamicSharedMemorySize, SMEM3);
    cudaFuncSetAttribute(gemm_mma<0,2,3>, cudaFuncAttributeMaxDynamicSharedMemorySize, SMEM3);
    cudaFuncSetAttribute(gemm_mma<0,3,1>, cudaFuncAttributeMaxDynamicSharedMemorySize, SMEM1);

    const size_t n1 = (size_t)BATCH * SEQ1 * DIM;

    // 0) mask compaction + operand prep
    build_idx<<<BATCH, 256>>>(mask, idxp, nbp);
    split_kernel<<<(unsigned)(n1 / 1024), 256>>>(input2, in2h, in2l);
    split_kernel<<<(unsigned)((size_t)DIM * DIM / 1024), 256>>>(weight, wh, wl);
    gather_split<<<dim3(SEQ1 / 32, DIM / 32, BATCH), 256>>>(
        input1, idxp, nbp, in1h, in1l, t1f);

    // 1) out1c[b,j,:] = in1c[b,j,:] @ W^T  (compacted M, split-bf16 out)
    gemm_mma<2,1,3><<<dim3(DIM / 128, SEQ1 / 128, BATCH), 256, SMEM3>>>(
        in1h, in1l, wh, wl, nullptr, o1h, o1l, nbp,
        DIM, DIM, DIM,
        (size_t)SEQ1 * DIM, 0, (size_t)SEQ1 * DIM);

    // 2) scoresT[b,t,j] = in2[b,t,:] . out1c[b,j,:]  (compacted N)
    gemm_mma<0,2,3><<<dim3(SEQ1 / 128, SEQ2 / 128, BATCH), 256, SMEM3>>>(
        in2h, in2l, o1h, o1l, scoresp, nullptr, nullptr, nbp,
        SEQ1, DIM, DIM,
        (size_t)SEQ2 * DIM, (size_t)SEQ1 * DIM, (size_t)SEQ2 * SEQ1);

    // 3) softmax over compacted j -> single fp16 P (zero-padded)
    softmax_rows<<<BATCH * SEQ2, 256>>>(scoresp, nbp, pf);

    // 4) out[b,t,d] = sum_j P[b,t,j] * in1c[b,j,d]  (compacted K, fp16 1-prod)
    gemm_mma<0,3,1><<<dim3(DIM / 128, SEQ2 / 128, BATCH), 256, SMEM1>>>(
        (const bf16*)pf, nullptr, (const bf16*)t1f, nullptr,
        out, nullptr, nullptr, nbp,
        DIM, SEQ1, SEQ1,
        (size_t)SEQ2 * SEQ1, (size_t)DIM * SEQ1, (size_t)SEQ2 * DIM);
}

// round 10
// speedup vs baseline: 2.8889x; 1.0131x over previous
#include <cuda_runtime.h>
#include <cuda_bf16.h>
#include <cuda_fp16.h>
#include <stdint.h>

#define BATCH 8
#define SEQ1  2048
#define SEQ2  2048
#define DIM   1024

using bf16 = __nv_bfloat16;

// ---------------- scratch (static __device__, zero-init, no allocation) -----
__device__ int    g_idx[BATCH * SEQ1];              // compacted s indices
__device__ int    g_nb[BATCH];                      // # unmasked rows per batch
__device__ bf16   g_in1h[(size_t)BATCH*SEQ1*DIM];   // compacted input1 split
__device__ bf16   g_in1l[(size_t)BATCH*SEQ1*DIM];
__device__ bf16   g_in2h[(size_t)BATCH*SEQ2*DIM];
__device__ bf16   g_in2l[(size_t)BATCH*SEQ2*DIM];
__device__ bf16   g_wh[(size_t)DIM*DIM];
__device__ bf16   g_wl[(size_t)DIM*DIM];
__device__ bf16   g_o1h[(size_t)BATCH*SEQ1*DIM];    // compacted out1 split
__device__ bf16   g_o1l[(size_t)BATCH*SEQ1*DIM];
__device__ __half g_t1f[(size_t)BATCH*DIM*SEQ1];    // compacted input1^T fp16
__device__ float  g_scores[(size_t)BATCH*SEQ2*SEQ1];
__device__ __half g_pf[(size_t)BATCH*SEQ2*SEQ1];    // probabilities fp16

__device__ __forceinline__ void split2(float x, bf16 &h, bf16 &l) {
    h = __float2bfloat16(x);
    l = __float2bfloat16(x - __bfloat162float(h));
}

// ---------------- mask compaction: per-batch ascending index list -----------
__global__ __launch_bounds__(256)
void build_idx(const unsigned* __restrict__ mask, int* __restrict__ idx,
               int* __restrict__ nb)
{
    const int b = blockIdx.x, tid = threadIdx.x;
    const int lane = tid & 31, wid = tid >> 5;
    const unsigned* mk = mask + (size_t)b * SEQ1;
    __shared__ int wsum[8];

    int bits[8], c = 0;
#pragma unroll
    for (int k = 0; k < 8; k++) {
        bits[k] = (mk[tid * 8 + k] != 0u) ? 1 : 0;
        c += bits[k];
    }
    int pre = c;
#pragma unroll
    for (int o = 1; o < 32; o <<= 1) {
        int n = __shfl_up_sync(0xffffffffu, pre, o);
        if (lane >= o) pre += n;
    }
    if (lane == 31) wsum[wid] = pre;
    __syncthreads();
    int woff = 0;
    for (int w = 0; w < wid; w++) woff += wsum[w];
    int pos = woff + pre - c;
#pragma unroll
    for (int k = 0; k < 8; k++)
        if (bits[k]) idx[b * SEQ1 + pos++] = tid * 8 + k;
    if (tid == 255) nb[b] = woff + pre;
}

// ---------------- split (fp32 -> hi/lo bf16), plain -------------------------
__global__ __launch_bounds__(256) void split_kernel(const float* __restrict__ x,
                                                    bf16* __restrict__ h,
                                                    bf16* __restrict__ l) {
    size_t i = ((size_t)blockIdx.x * 256 + threadIdx.x) * 4;
    float4 v = *(const float4*)(x + i);
    bf16 h0,h1,h2,h3,l0,l1,l2,l3;
    split2(v.x,h0,l0); split2(v.y,h1,l1); split2(v.z,h2,l2); split2(v.w,h3,l3);
    __nv_bfloat162 a, b;
    a.x=h0; a.y=h1; b.x=h2; b.y=h3;
    ((__nv_bfloat162*)(h+i))[0] = a; ((__nv_bfloat162*)(h+i))[1] = b;
    a.x=l0; a.y=l1; b.x=l2; b.y=l3;
    ((__nv_bfloat162*)(l+i))[0] = a; ((__nv_bfloat162*)(l+i))[1] = b;
}

// ---------------- gather + split + transpose of input1 (compacted) ----------
__global__ __launch_bounds__(256)
void gather_split(const float* __restrict__ x, const int* __restrict__ idxp,
                  const int* __restrict__ nbp,
                  bf16* __restrict__ ch, bf16* __restrict__ cl,
                  __half* __restrict__ tf)
{
    const int b  = blockIdx.z;
    const int j0 = blockIdx.x * 32, d0 = blockIdx.y * 32;
    const int nb = nbp[b];
    const int npad = (nb + 127) & ~127;
    if (j0 >= npad) return;

    const int tx = threadIdx.x & 31, ty = threadIdx.x >> 5;
    __shared__ float t[32][33];
    __shared__ int rows[32];
    if (threadIdx.x < 32)
        rows[threadIdx.x] =
            (j0 + threadIdx.x < nb) ? idxp[b * SEQ1 + j0 + threadIdx.x] : -1;
    __syncthreads();
#pragma unroll
    for (int k = 0; k < 4; k++) {
        const int j = ty + 8 * k;
        const int s = rows[j];
        t[j][tx] = (s >= 0) ? x[((size_t)b * SEQ1 + s) * DIM + d0 + tx] : 0.0f;
    }
    __syncthreads();
#pragma unroll
    for (int k = 0; k < 4; k++) {        // normal orientation, bf16 split
        const int j = ty + 8 * k;
        bf16 h, l; split2(t[j][tx], h, l);
        const size_t o = ((size_t)b * SEQ1 + j0 + j) * DIM + d0 + tx;
        ch[o] = h; cl[o] = l;
    }
#pragma unroll
    for (int k = 0; k < 4; k++) {        // transposed orientation, fp16
        const size_t o = ((size_t)b * DIM + d0 + ty + 8 * k) * SEQ1 + j0 + tx;
        tf[o] = __float2half(t[tx][ty + 8 * k]);
    }
}

// ---------------- PTX helpers ----------------
#define CP16(dst, src) asm volatile("cp.async.cg.shared.global [%0], [%1], 16;\n" :: "r"(dst), "l"(src))
#define CP_COMMIT()    asm volatile("cp.async.commit_group;\n")
#define CP_WAIT2()     asm volatile("cp.async.wait_group 2;\n")
#define CP_WAIT1()     asm volatile("cp.async.wait_group 1;\n")
#define CP_WAIT0()     asm volatile("cp.async.wait_group 0;\n")

#define MMA_BF16(d, a, b) asm volatile( \
  "mma.sync.aligned.m16n8k16.row.col.f32.bf16.bf16.f32 " \
  "{%0,%1,%2,%3},{%4,%5,%6,%7},{%8,%9},{%0,%1,%2,%3};\n" \
  : "+f"(d[0]), "+f"(d[1]), "+f"(d[2]), "+f"(d[3]) \
  : "r"(a[0]), "r"(a[1]), "r"(a[2]), "r"(a[3]), "r"(b[0]), "r"(b[1]))

#define MMA_F16(d, a, b) asm volatile( \
  "mma.sync.aligned.m16n8k16.row.col.f32.f16.f16.f32 " \
  "{%0,%1,%2,%3},{%4,%5,%6,%7},{%8,%9},{%0,%1,%2,%3};\n" \
  : "+f"(d[0]), "+f"(d[1]), "+f"(d[2]), "+f"(d[3]) \
  : "r"(a[0]), "r"(a[1]), "r"(a[2]), "r"(a[3]), "r"(b[0]), "r"(b[1]))

#define LDSM_X4(r0, r1, r2, r3, addr) asm volatile( \
  "ldmatrix.sync.aligned.m8n8.x4.shared.b16 {%0,%1,%2,%3}, [%4];\n" \
  : "=r"(r0), "=r"(r1), "=r"(r2), "=r"(r3) : "r"(addr))

// ---------------------------------------------------------------------------
// HMMA NT GEMM (round-9 proven core, now 4-stage pipeline / 3 chunks in
// flight): C = A*B^T. 128x128 tile, BK=16, 8 warps (64x32 each), cp.async,
// ldmatrix.x4, product-major order.
//   PROD=3: split-bf16 3-product, 4 operand arrays.  PROD=1: fp16 1-product.
//   EPI=0: fp32 out.  EPI=2: split-bf16 out.
//   BND=1: skip m0 >= pad128(nb).  BND=2: skip n0 >= pad128(nb).
//   BND=3: K = pad16(nb).   Ks = row stride of A/B.
// ---------------------------------------------------------------------------
template<int EPI, int BND, int PROD>
__global__ __launch_bounds__(256, 2)
void gemm_mma(const bf16* __restrict__ Ahg, const bf16* __restrict__ Alg,
              const bf16* __restrict__ Bhg, const bf16* __restrict__ Blg,
              float* __restrict__ Cfg, bf16* __restrict__ Chg, bf16* __restrict__ Clg,
              const int* __restrict__ nbp,
              int N, int K, int Ks,
              size_t sA, size_t sB, size_t sC)
{
    extern __shared__ __align__(16) char dsm[];
    const uint32_t smem0 = (uint32_t)__cvta_generic_to_shared(dsm);
    constexpr uint32_t ARR = 6144u;                       // 128 x 24 halves x 2B
    constexpr uint32_t NARR = (PROD == 3) ? 4u : 2u;
    constexpr uint32_t STAGE = NARR * ARR;
    constexpr uint32_t BOFF = (PROD == 3) ? 2u * ARR : ARR;

    const int tid  = threadIdx.x;
    const int warp = tid >> 5, lane = tid & 31;
    const int wm = warp >> 2, wn = warp & 3;
    const int g  = lane >> 2, tq = lane & 3;
    const int bz = blockIdx.z;
    const int m0 = blockIdx.y * 128, n0 = blockIdx.x * 128;

    int Klogic = K;
    if (BND) {
        const int nb = nbp[bz];
        const int npad = (nb + 127) & ~127;
        if (BND == 1 && m0 >= npad) return;
        if (BND == 2 && n0 >= npad) return;
        if (BND == 3) Klogic = (nb + 15) & ~15;
    }

    const bf16* Ah = Ahg + (size_t)bz * sA + (size_t)m0 * Ks;
    const bf16* Al = (PROD == 3) ? Alg + (size_t)bz * sA + (size_t)m0 * Ks : nullptr;
    const bf16* Bh = Bhg + (size_t)bz * sB + (size_t)n0 * Ks;
    const bf16* Bl = (PROD == 3) ? Blg + (size_t)bz * sB + (size_t)n0 * Ks : nullptr;

    const int r_ = tid >> 1, u_ = tid & 1;
    const uint32_t offc = (uint32_t)(r_ * 48 + u_ * 16);

    const uint32_t aOff =
        (uint32_t)(((lane & 15) * 24 + ((lane >> 4) & 1) * 8) * 2);
    const uint32_t bOffL =
        (uint32_t)((((lane & 7) + ((lane >> 4) & 1) * 8) * 24 +
                    ((lane >> 3) & 1) * 8) * 2);

    float acc[4][4][4];
#pragma unroll
    for (int mt = 0; mt < 4; mt++)
#pragma unroll
        for (int nt = 0; nt < 4; nt++)
#pragma unroll
            for (int c = 0; c < 4; c++) acc[mt][nt][c] = 0.0f;

    const int NC = Klogic >> 4;

    auto issue = [&](int stg, int kk) {
        const uint32_t sb_ = smem0 + (uint32_t)stg * STAGE;
        const size_t go_ = (size_t)r_ * Ks + kk + u_ * 8;
        CP16(sb_ + offc, Ah + go_);
        if (PROD == 3) CP16(sb_ + ARR + offc, Al + go_);
        CP16(sb_ + BOFF + offc, Bh + go_);
        if (PROD == 3) CP16(sb_ + 3u * ARR + offc, Bl + go_);
        CP_COMMIT();
    };

    // 4-stage prologue: 3 chunks in flight
    issue(0, 0);
    if (NC > 1) issue(1, 16);
    if (NC > 2) issue(2, 32);

    for (int i = 0; i < NC; i++) {
        // wait until chunk i has landed (pending groups <= committed-ahead)
        if (i + 2 < NC)      { CP_WAIT2(); }
        else if (i + 1 < NC) { CP_WAIT1(); }
        else                 { CP_WAIT0(); }
        __syncthreads();
        if (i + 3 < NC) issue((i + 3) & 3, (i + 3) << 4);

        const uint32_t stb = smem0 + (uint32_t)(i & 3) * STAGE;

        uint32_t bh4[2][4], bl4[2][4];
#pragma unroll
        for (int p = 0; p < 2; p++) {
            const uint32_t bo =
                stb + BOFF + (uint32_t)((wn * 32 + p * 16) * 48) + bOffL;
            LDSM_X4(bh4[p][0], bh4[p][1], bh4[p][2], bh4[p][3], bo);
            if (PROD == 3)
                LDSM_X4(bl4[p][0], bl4[p][1], bl4[p][2], bl4[p][3], bo + ARR);
        }
        uint32_t ah[4][4];
#pragma unroll
        for (int mt = 0; mt < 4; mt++) {
            const uint32_t ao =
                stb + (uint32_t)((wm * 64 + mt * 16) * 48) + aOff;
            LDSM_X4(ah[mt][0], ah[mt][1], ah[mt][2], ah[mt][3], ao);
        }

        // phase 1: Ah*Bh
#pragma unroll
        for (int mt = 0; mt < 4; mt++)
#pragma unroll
            for (int nt = 0; nt < 4; nt++) {
                if (PROD == 3) {
                    MMA_BF16(acc[mt][nt], ah[mt], (&bh4[nt >> 1][(nt & 1) * 2]));
                } else {
                    MMA_F16(acc[mt][nt], ah[mt], (&bh4[nt >> 1][(nt & 1) * 2]));
                }
            }
        if (PROD == 3) {
            // phase 2: Ah*Bl
#pragma unroll
            for (int mt = 0; mt < 4; mt++)
#pragma unroll
                for (int nt = 0; nt < 4; nt++)
                    MMA_BF16(acc[mt][nt], ah[mt], (&bl4[nt >> 1][(nt & 1) * 2]));
            // phase 3: Al*Bh
#pragma unroll
            for (int mt = 0; mt < 4; mt++) {
                const uint32_t ao =
                    stb + ARR + (uint32_t)((wm * 64 + mt * 16) * 48) + aOff;
                uint32_t al[4];
                LDSM_X4(al[0], al[1], al[2], al[3], ao);
#pragma unroll
                for (int nt = 0; nt < 4; nt++)
                    MMA_BF16(acc[mt][nt], al, (&bh4[nt >> 1][(nt & 1) * 2]));
            }
        }
    }

    // ---------------- epilogue ----------------
    float* Cf = (EPI == 0) ? Cfg + (size_t)bz * sC : nullptr;
    bf16*  Ch = (EPI == 2) ? Chg + (size_t)bz * sC : nullptr;
    bf16*  Cl = (EPI == 2) ? Clg + (size_t)bz * sC : nullptr;

#pragma unroll
    for (int mt = 0; mt < 4; mt++) {
        const int r0 = m0 + wm * 64 + mt * 16 + g;
#pragma unroll
        for (int nt = 0; nt < 4; nt++) {
            const int col = n0 + wn * 32 + nt * 8 + tq * 2;
            const float c0 = acc[mt][nt][0], c1 = acc[mt][nt][1];
            const float c2 = acc[mt][nt][2], c3 = acc[mt][nt][3];
            if (EPI == 0) {
                *(float2*)(Cf + (size_t)r0 * N + col)       = make_float2(c0, c1);
                *(float2*)(Cf + (size_t)(r0 + 8) * N + col) = make_float2(c2, c3);
            } else {
                bf16 h0,h1,h2,h3,l0,l1,l2,l3;
                split2(c0,h0,l0); split2(c1,h1,l1); split2(c2,h2,l2); split2(c3,h3,l3);
                __nv_bfloat162 t;
                t.x=h0; t.y=h1; *(__nv_bfloat162*)(Ch + (size_t)r0*N + col)     = t;
                t.x=h2; t.y=h3; *(__nv_bfloat162*)(Ch + (size_t)(r0+8)*N + col) = t;
                t.x=l0; t.y=l1; *(__nv_bfloat162*)(Cl + (size_t)r0*N + col)     = t;
                t.x=l2; t.y=l3; *(__nv_bfloat162*)(Cl + (size_t)(r0+8)*N + col) = t;
            }
        }
    }
}

// ---------------------------------------------------------------------------
// Variable-length row softmax over compacted scores [b,t,j], j in [0, nb).
// Writes single-fp16 probabilities; zero-fills padding up to pad128(nb).
// ---------------------------------------------------------------------------
__global__ __launch_bounds__(256)
void softmax_rows(const float* __restrict__ scores, const int* __restrict__ nbp,
                  __half* __restrict__ pf)
{
    const int tid = threadIdx.x;
    const int b = blockIdx.x >> 11;         // SEQ2 = 2048 rows per batch
    const int nb = nbp[b];
    const int npad = (nb + 127) & ~127;
    const size_t base = (size_t)blockIdx.x * SEQ1;
    const float* row = scores + base;

    float v[8];
    float mx = -3.4e38f;
#pragma unroll
    for (int i = 0; i < 8; i++) {
        const int j = tid + (i << 8);
        v[i] = (j < nb) ? row[j] : -3.4e38f;
        mx = fmaxf(mx, v[i]);
    }
#pragma unroll
    for (int o = 16; o > 0; o >>= 1)
        mx = fmaxf(mx, __shfl_xor_sync(0xffffffffu, mx, o));

    __shared__ float smax[8];
    __shared__ float ssum[8];
    if ((tid & 31) == 0) smax[tid >> 5] = mx;
    __syncthreads();
    mx = smax[0];
#pragma unroll
    for (int w = 1; w < 8; w++) mx = fmaxf(mx, smax[w]);

    float s = 0.0f;
#pragma unroll
    for (int i = 0; i < 8; i++) {
        const int j = tid + (i << 8);
        v[i] = (j < nb) ? __expf(v[i] - mx) : 0.0f;
        s += v[i];
    }
#pragma unroll
    for (int o = 16; o > 0; o >>= 1)
        s += __shfl_xor_sync(0xffffffffu, s, o);
    if ((tid & 31) == 0) ssum[tid >> 5] = s;
    __syncthreads();
    s = ssum[0];
#pragma unroll
    for (int w = 1; w < 8; w++) s += ssum[w];

    const float inv = 1.0f / s;
#pragma unroll
    for (int i = 0; i < 8; i++) {
        const int j = tid + (i << 8);
        if (j < npad)
            pf[base + j] = __float2half((j < nb) ? v[i] * inv : 0.0f);
    }
}

// ---------------------------------------------------------------------------
extern "C" void kernel_launch(void* const* d_in, const int* in_sizes, int n_in,
                              void* d_out, int out_size)
{
    const float*        input1 = (const float*)d_in[0];          // [B,S1,D]
    const float*        input2 = (const float*)d_in[1];          // [B,S2,D]
    const unsigned int* mask   = (const unsigned int*)d_in[2];   // [B,S1] words
    const float*        weight = (const float*)d_in[3];          // [D,D]
    float*              out    = (float*)d_out;                  // [B,S2,D]

    bf16 *in1h,*in1l,*in2h,*in2l,*wh,*wl,*o1h,*o1l;
    __half *t1f, *pf;
    float *scoresp; int *idxp, *nbp;
    cudaGetSymbolAddress((void**)&idxp, g_idx);
    cudaGetSymbolAddress((void**)&nbp,  g_nb);
    cudaGetSymbolAddress((void**)&in1h, g_in1h);
    cudaGetSymbolAddress((void**)&in1l, g_in1l);
    cudaGetSymbolAddress((void**)&in2h, g_in2h);
    cudaGetSymbolAddress((void**)&in2l, g_in2l);
    cudaGetSymbolAddress((void**)&wh,  g_wh);
    cudaGetSymbolAddress((void**)&wl,  g_wl);
    cudaGetSymbolAddress((void**)&o1h, g_o1h);
    cudaGetSymbolAddress((void**)&o1l, g_o1l);
    cudaGetSymbolAddress((void**)&t1f, g_t1f);
    cudaGetSymbolAddress((void**)&pf,  g_pf);
    cudaGetSymbolAddress((void**)&scoresp, g_scores);

    const int SMEM3 = 98304;   // PROD=3: 4 stages x 4 arrays x 6144B
    const int SMEM1 = 49152;   // PROD=1: 4 stages x 2 arrays x 6144B
    cudaFuncSetAttribute(gemm_mma<2,1,3>, cudaFuncAttributeMaxDynamicSharedMemorySize, SMEM3);
    cudaFuncSetAttribute(gemm_mma<0,2,3>, cudaFuncAttributeMaxDynamicSharedMemorySize, SMEM3);
    cudaFuncSetAttribute(gemm_mma<0,3,1>, cudaFuncAttributeMaxDynamicSharedMemorySize, SMEM1);

    const size_t n1 = (size_t)BATCH * SEQ1 * DIM;

    // 0) mask compaction + operand prep
    build_idx<<<BATCH, 256>>>(mask, idxp, nbp);
    split_kernel<<<(unsigned)(n1 / 1024), 256>>>(input2, in2h, in2l);
    split_kernel<<<(unsigned)((size_t)DIM * DIM / 1024), 256>>>(weight, wh, wl);
    gather_split<<<dim3(SEQ1 / 32, DIM / 32, BATCH), 256>>>(
        input1, idxp, nbp, in1h, in1l, t1f);

    // 1) out1c[b,j,:] = in1c[b,j,:] @ W^T  (compacted M, split-bf16 out)
    gemm_mma<2,1,3><<<dim3(DIM / 128, SEQ1 / 128, BATCH), 256, SMEM3>>>(
        in1h, in1l, wh, wl, nullptr, o1h, o1l, nbp,
        DIM, DIM, DIM,
        (size_t)SEQ1 * DIM, 0, (size_t)SEQ1 * DIM);

    // 2) scoresT[b,t,j] = in2[b,t,:] . out1c[b,j,:]  (compacted N)
    gemm_mma<0,2,3><<<dim3(SEQ1 / 128, SEQ2 / 128, BATCH), 256, SMEM3>>>(
        in2h, in2l, o1h, o1l, scoresp, nullptr, nullptr, nbp,
        SEQ1, DIM, DIM,
        (size_t)SEQ2 * DIM, (size_t)SEQ1 * DIM, (size_t)SEQ2 * SEQ1);

    // 3) softmax over compacted j -> single fp16 P (zero-padded)
    softmax_rows<<<BATCH * SEQ2, 256>>>(scoresp, nbp, pf);

    // 4) out[b,t,d] = sum_j P[b,t,j] * in1c[b,j,d]  (compacted K, fp16 1-prod)
    gemm_mma<0,3,1><<<dim3(DIM / 128, SEQ2 / 128, BATCH), 256, SMEM1>>>(
        (const bf16*)pf, nullptr, (const bf16*)t1f, nullptr,
        out, nullptr, nullptr, nbp,
        DIM, SEQ1, SEQ1,
        (size_t)SEQ2 * SEQ1, (size_t)DIM * SEQ1, (size_t)SEQ2 * DIM);
}